// round 6
// baseline (speedup 1.0000x reference)
#include <cuda_runtime.h>
#include <cuda_bf16.h>
#include <cstdint>
#include <math.h>

#define B_   2
#define S_   2048
#define HID_ 2048
#define NH_  16
#define HD_  128
#define KDIM 2048

typedef __nv_bfloat16 bf16;

// ---- persistent split buffers ----
__device__ bf16 g_xh[(size_t)B_ * S_ * HID_];
__device__ bf16 g_xl[(size_t)B_ * S_ * HID_];
__device__ bf16 g_wqh[(size_t)3 * HID_ * HID_];
__device__ bf16 g_wql[(size_t)3 * HID_ * HID_];
__device__ bf16 g_woh[(size_t)HID_ * HID_];
__device__ bf16 g_wol[(size_t)HID_ * HID_];
__device__ bf16 g_qkvh[(size_t)3 * B_ * NH_ * S_ * HD_];  // [which][b][h][s][d]
__device__ bf16 g_qkvl[(size_t)3 * B_ * NH_ * S_ * HD_];
__device__ bf16 g_ctxh[(size_t)B_ * S_ * HID_];           // [b][s][h][d]
__device__ bf16 g_ctxl[(size_t)B_ * S_ * HID_];

// ---------------- helpers ----------------
__device__ __forceinline__ uint32_t s2u(const void* p) {
    return (uint32_t)__cvta_generic_to_shared(p);
}
__device__ __forceinline__ uint32_t packbf(float lo, float hi) {
    uint32_t r;
    asm("cvt.rn.bf16x2.f32 %0, %1, %2;" : "=r"(r) : "f"(hi), "f"(lo));
    return r;
}

#define MMA_BF16(d, a, b)                                                     \
    asm volatile(                                                             \
        "mma.sync.aligned.m16n8k16.row.col.f32.bf16.bf16.f32 "                \
        "{%0,%1,%2,%3}, {%4,%5,%6,%7}, {%8,%9}, {%0,%1,%2,%3};\n"             \
        : "+f"((d)[0]), "+f"((d)[1]), "+f"((d)[2]), "+f"((d)[3])              \
        : "r"((a)[0]), "r"((a)[1]), "r"((a)[2]), "r"((a)[3]),                 \
          "r"((b)[0]), "r"((b)[1]))

#define LDSM_X4(r, addr)                                                      \
    asm volatile("ldmatrix.sync.aligned.m8n8.x4.shared.b16 {%0,%1,%2,%3}, [%4];" \
                 : "=r"((r)[0]), "=r"((r)[1]), "=r"((r)[2]), "=r"((r)[3])     \
                 : "r"(addr))

#define LDSM_X4T(r, addr)                                                     \
    asm volatile("ldmatrix.sync.aligned.m8n8.x4.trans.shared.b16 {%0,%1,%2,%3}, [%4];" \
                 : "=r"((r)[0]), "=r"((r)[1]), "=r"((r)[2]), "=r"((r)[3])     \
                 : "r"(addr))

#define CP_ASYNC16(dst, src)                                                  \
    asm volatile("cp.async.cg.shared.global [%0], [%1], 16;" ::               \
                 "r"(dst), "l"(src))
#define CP_COMMIT() asm volatile("cp.async.commit_group;" ::: "memory")
#define CP_WAIT1()  asm volatile("cp.async.wait_group 1;" ::: "memory")

// ---------------------------------------------------------------------------
// Split fp32 -> bf16 hi/lo (prep).
// ---------------------------------------------------------------------------
__global__ __launch_bounds__(256)
void split_kernel(const float* __restrict__ src, bf16* __restrict__ h,
                  bf16* __restrict__ l, int n4) {
    int i = blockIdx.x * 256 + threadIdx.x;
    if (i >= n4) return;
    float4 v = *(const float4*)&src[(size_t)i * 4];
    float f[4] = {v.x, v.y, v.z, v.w};
    float hf[4], lf[4];
#pragma unroll
    for (int e = 0; e < 4; e++) {
        hf[e] = __bfloat162float(__float2bfloat16(f[e]));
        lf[e] = f[e] - hf[e];
    }
    *(uint2*)&h[(size_t)i * 4] = make_uint2(packbf(hf[0], hf[1]), packbf(hf[2], hf[3]));
    *(uint2*)&l[(size_t)i * 4] = make_uint2(packbf(lf[0], lf[1]), packbf(lf[2], lf[3]));
}

// ---------------------------------------------------------------------------
// Pipelined split-bf16 GEMM: C[m][n] = sum_k A[m][k]*W[n][k]
// BM=BN=128, BK=16/stage, 2-stage cp.async double buffer, 256 thr, 8 warps.
// smem: 2 stages x 4 arrays x [128][24] bf16 = 49152 B  -> 2 CTAs/SM.
// MODE 0: scatter split bf16 into g_qkvh/g_qkvl.  MODE 1: fp32 out.
// ---------------------------------------------------------------------------
#define GST 24                       // row stride (16 + 8 pad)
#define ARRE (128 * GST)             // elems per array
#define STAGEE (4 * ARRE)            // elems per stage
#define GEMM_SMEM (2 * STAGEE * 2)   // bytes = 49152

template <int MODE>
__global__ __launch_bounds__(256, 2)
void gemm_bf16_kernel(const bf16* __restrict__ Agh, const bf16* __restrict__ Agl,
                      const bf16* __restrict__ Bgh, const bf16* __restrict__ Bgl,
                      float* __restrict__ Cout) {
    extern __shared__ bf16 smem[];
    const int m0 = blockIdx.y * 128;
    const int n0 = blockIdx.x * 128;
    const int tid = threadIdx.x;
    const int lane = tid & 31;
    const int warp = tid >> 5;
    const int warpM = warp & 3;
    const int warpN = warp >> 2;

    const uint32_t sbase = s2u(smem);
    const int g = lane >> 2;
    const int qp = lane & 3;
    const int frow = lane & 15;
    const int fcol = (lane >> 4) << 3;

    // per-thread load slot: row = tid>>1 (0..127), half = tid&1 (8 elems)
    const int lrow = tid >> 1;
    const int lhalf = tid & 1;
    const size_t gaoff = (size_t)(m0 + lrow) * KDIM + lhalf * 8;
    const size_t gboff = (size_t)(n0 + lrow) * KDIM + lhalf * 8;
    const uint32_t dstoff = (lrow * GST + lhalf * 8) * 2;

    float C[2][8][4];
#pragma unroll
    for (int mt = 0; mt < 2; mt++)
#pragma unroll
        for (int nt = 0; nt < 8; nt++)
#pragma unroll
            for (int r = 0; r < 4; r++) C[mt][nt][r] = 0.f;

#define ISSUE(s)                                                              \
    do {                                                                      \
        int buf_ = (s) & 1;                                                   \
        int k0_ = (s) * 16;                                                   \
        uint32_t d_ = sbase + buf_ * (STAGEE * 2) + dstoff;                   \
        CP_ASYNC16(d_,                Agh + gaoff + k0_);                     \
        CP_ASYNC16(d_ + ARRE * 2,     Agl + gaoff + k0_);                     \
        CP_ASYNC16(d_ + ARRE * 4,     Bgh + gboff + k0_);                     \
        CP_ASYNC16(d_ + ARRE * 6,     Bgl + gboff + k0_);                     \
        CP_COMMIT();                                                          \
    } while (0)

    ISSUE(0);
    ISSUE(1);

    const int NSTAGES = KDIM / 16;   // 128
#pragma unroll 1
    for (int s = 0; s < NSTAGES; s++) {
        CP_WAIT1();
        __syncthreads();

        const int buf = s & 1;
        const uint32_t uAh = sbase + buf * (STAGEE * 2);
        const uint32_t uAl = uAh + ARRE * 2;
        const uint32_t uBh = uAh + ARRE * 4;
        const uint32_t uBl = uAh + ARRE * 6;

        uint32_t a_hi[2][4], a_lo[2][4];
#pragma unroll
        for (int mt = 0; mt < 2; mt++) {
            uint32_t off = ((warpM * 32 + mt * 16 + frow) * GST + fcol) * 2;
            LDSM_X4(a_hi[mt], uAh + off);
            LDSM_X4(a_lo[mt], uAl + off);
        }
#pragma unroll
        for (int p = 0; p < 4; p++) {
            uint32_t off = ((warpN * 64 + p * 16 + frow) * GST + fcol) * 2;
            uint32_t kb_h[4], kb_l[4];
            LDSM_X4(kb_h, uBh + off);
            LDSM_X4(kb_l, uBl + off);
            uint32_t bh0[2] = {kb_h[0], kb_h[2]};
            uint32_t bh1[2] = {kb_h[1], kb_h[3]};
            uint32_t bl0[2] = {kb_l[0], kb_l[2]};
            uint32_t bl1[2] = {kb_l[1], kb_l[3]};
#pragma unroll
            for (int mt = 0; mt < 2; mt++) {
                MMA_BF16(C[mt][2 * p], a_hi[mt], bh0);
                MMA_BF16(C[mt][2 * p], a_lo[mt], bh0);
                MMA_BF16(C[mt][2 * p], a_hi[mt], bl0);
                MMA_BF16(C[mt][2 * p + 1], a_hi[mt], bh1);
                MMA_BF16(C[mt][2 * p + 1], a_lo[mt], bh1);
                MMA_BF16(C[mt][2 * p + 1], a_hi[mt], bl1);
            }
        }
        __syncthreads();
        if (s + 2 < NSTAGES) ISSUE(s + 2);
    }
#undef ISSUE

    // epilogue
#pragma unroll
    for (int mt = 0; mt < 2; mt++) {
#pragma unroll
        for (int nt = 0; nt < 8; nt++) {
            int gm0 = m0 + warpM * 32 + mt * 16 + g;
            int gn = n0 + warpN * 64 + nt * 8 + qp * 2;
            if (MODE == 0) {
                int which = gn >> 11;
                int rem = gn & 2047;
                int h = rem >> 7;
                int d = rem & 127;
#pragma unroll
                for (int rr = 0; rr < 2; rr++) {
                    int gm = gm0 + rr * 8;
                    int b = gm >> 11;
                    int s2 = gm & 2047;
                    size_t off = (size_t)which * ((size_t)B_ * NH_ * S_ * HD_) +
                                 (((size_t)(b * NH_ + h)) * S_ + s2) * HD_ + d;
                    float v0 = C[mt][nt][rr * 2], v1 = C[mt][nt][rr * 2 + 1];
                    float h0 = __bfloat162float(__float2bfloat16(v0));
                    float h1 = __bfloat162float(__float2bfloat16(v1));
                    *(uint32_t*)&g_qkvh[off] = packbf(h0, h1);
                    *(uint32_t*)&g_qkvl[off] = packbf(v0 - h0, v1 - h1);
                }
            } else {
                *(float2*)&Cout[(size_t)gm0 * HID_ + gn] =
                    make_float2(C[mt][nt][0], C[mt][nt][1]);
                *(float2*)&Cout[(size_t)(gm0 + 8) * HID_ + gn] =
                    make_float2(C[mt][nt][2], C[mt][nt][3]);
            }
        }
    }
}

// ---------------------------------------------------------------------------
// RoPE in-place on split Q and K halves.
// ---------------------------------------------------------------------------
__global__ __launch_bounds__(256)
void rope_kernel(const float* __restrict__ cosT, const float* __restrict__ sinT) {
    long long t = (long long)blockIdx.x * 256 + threadIdx.x;
    int d = (int)(t & 63);
    long long row = t >> 6;
    int s = (int)(row % S_);
    bf16* ph = g_qkvh + row * HD_;
    bf16* pl = g_qkvl + row * HD_;
    float x1 = __bfloat162float(ph[d]) + __bfloat162float(pl[d]);
    float x2 = __bfloat162float(ph[d + 64]) + __bfloat162float(pl[d + 64]);
    float c1 = cosT[s * HD_ + d];
    float s1 = sinT[s * HD_ + d];
    float c2 = cosT[s * HD_ + d + 64];
    float s2 = sinT[s * HD_ + d + 64];
    float r1 = x1 * c1 - x2 * s1;
    float r2 = x2 * c2 + x1 * s2;
    float h1 = __bfloat162float(__float2bfloat16(r1));
    float h2 = __bfloat162float(__float2bfloat16(r2));
    ph[d] = __float2bfloat16(h1);
    pl[d] = __float2bfloat16(r1 - h1);
    ph[d + 64] = __float2bfloat16(h2);
    pl[d + 64] = __float2bfloat16(r2 - h2);
}

// ---------------------------------------------------------------------------
// Split-bf16 tensor-core causal flash attention. BQ=128, BK=64, 256 threads.
// ---------------------------------------------------------------------------
#define STQ 136
#define ATTN_SMEM ((2 * 128 + 4 * 64) * STQ * 2)

__global__ __launch_bounds__(256, 1)
void attn_mma_kernel() {
    extern __shared__ char smraw[];
    bf16* sQh = (bf16*)smraw;
    bf16* sQl = sQh + 128 * STQ;
    bf16* sKh = sQl + 128 * STQ;
    bf16* sKl = sKh + 64 * STQ;
    bf16* sVh = sKl + 64 * STQ;
    bf16* sVl = sVh + 64 * STQ;

    const int tid = threadIdx.x;
    const int lane = tid & 31;
    const int w = tid >> 5;
    const int qp = lane & 3;
    const int g = lane >> 2;
    const int frow = lane & 15;
    const int fcol = (lane >> 4) << 3;

    const int qt = blockIdx.x;
    const int bh = blockIdx.y;
    const int b = bh >> 4;
    const int h = bh & 15;
    const int q0 = qt * 128;

    const size_t hs = (size_t)S_ * HD_;
    const bf16* Qh = g_qkvh + (size_t)bh * hs;
    const bf16* Ql = g_qkvl + (size_t)bh * hs;
    const bf16* Kh = g_qkvh + (size_t)(B_ * NH_ + bh) * hs;
    const bf16* Kl = g_qkvl + (size_t)(B_ * NH_ + bh) * hs;
    const bf16* Vh = g_qkvh + (size_t)(2 * B_ * NH_ + bh) * hs;
    const bf16* Vl = g_qkvl + (size_t)(2 * B_ * NH_ + bh) * hs;

#pragma unroll
    for (int i = 0; i < 8; i++) {
        int idx = tid + i * 256;
        int r = idx >> 4;
        int d = (idx & 15) * 8;
        size_t ga = (size_t)(q0 + r) * HD_ + d;
        *(uint4*)&sQh[r * STQ + d] = *(const uint4*)&Qh[ga];
        *(uint4*)&sQl[r * STQ + d] = *(const uint4*)&Ql[ga];
    }

    const uint32_t uQh = s2u(sQh), uQl = s2u(sQl);
    const uint32_t uKh = s2u(sKh), uKl = s2u(sKl);
    const uint32_t uVh = s2u(sVh), uVl = s2u(sVl);

    float O[16][4];
#pragma unroll
    for (int t = 0; t < 16; t++)
#pragma unroll
        for (int r = 0; r < 4; r++) O[t][r] = 0.f;
    float m0 = -1e30f, m1 = -1e30f, l0 = 0.f, l1 = 0.f;

    const float sc = 0.08838834764831845f;
    const int row0 = q0 + w * 16 + g;
    const int row1 = row0 + 8;

    __syncthreads();

    const int ktn = (q0 + 128) >> 6;
    for (int kt = 0; kt < ktn; kt++) {
        const int k0 = kt * 64;
#pragma unroll
        for (int i = 0; i < 4; i++) {
            int idx = tid + i * 256;
            int r = idx >> 4;
            int d = (idx & 15) * 8;
            size_t ga = (size_t)(k0 + r) * HD_ + d;
            *(uint4*)&sKh[r * STQ + d] = *(const uint4*)&Kh[ga];
            *(uint4*)&sKl[r * STQ + d] = *(const uint4*)&Kl[ga];
            *(uint4*)&sVh[r * STQ + d] = *(const uint4*)&Vh[ga];
            *(uint4*)&sVl[r * STQ + d] = *(const uint4*)&Vl[ga];
        }
        __syncthreads();

        const bool active = (k0 <= q0 + w * 16 + 15);
        if (active) {
            float S[8][4];
#pragma unroll
            for (int t = 0; t < 8; t++)
#pragma unroll
                for (int r = 0; r < 4; r++) S[t][r] = 0.f;

#pragma unroll
            for (int kc = 0; kc < 8; kc++) {
                const int col = kc * 16 + fcol;
                uint32_t qh[4], ql[4];
                uint32_t qoff = ((w * 16 + frow) * STQ + col) * 2;
                LDSM_X4(qh, uQh + qoff);
                LDSM_X4(ql, uQl + qoff);
#pragma unroll
                for (int p = 0; p < 4; p++) {
                    uint32_t koff = ((p * 16 + frow) * STQ + col) * 2;
                    uint32_t kh[4], kl[4];
                    LDSM_X4(kh, uKh + koff);
                    LDSM_X4(kl, uKl + koff);
                    uint32_t bh0[2] = {kh[0], kh[2]};
                    uint32_t bh1[2] = {kh[1], kh[3]};
                    uint32_t bl0[2] = {kl[0], kl[2]};
                    uint32_t bl1[2] = {kl[1], kl[3]};
                    MMA_BF16(S[2 * p], qh, bh0);
                    MMA_BF16(S[2 * p], ql, bh0);
                    MMA_BF16(S[2 * p], qh, bl0);
                    MMA_BF16(S[2 * p + 1], qh, bh1);
                    MMA_BF16(S[2 * p + 1], ql, bh1);
                    MMA_BF16(S[2 * p + 1], qh, bl1);
                }
            }

            const bool maskneed = (k0 + 63 > row0);
#pragma unroll
            for (int t = 0; t < 8; t++) {
                int c0 = k0 + 8 * t + 2 * qp;
#pragma unroll
                for (int r = 0; r < 4; r++) {
                    S[t][r] *= sc;
                    if (maskneed) {
                        int colg = c0 + (r & 1);
                        int rowg = (r < 2) ? row0 : row1;
                        if (colg > rowg) S[t][r] = -1e9f;
                    }
                }
            }

            float rm0 = -1e30f, rm1 = -1e30f;
#pragma unroll
            for (int t = 0; t < 8; t++) {
                rm0 = fmaxf(rm0, fmaxf(S[t][0], S[t][1]));
                rm1 = fmaxf(rm1, fmaxf(S[t][2], S[t][3]));
            }
            rm0 = fmaxf(rm0, __shfl_xor_sync(0xffffffffu, rm0, 1));
            rm0 = fmaxf(rm0, __shfl_xor_sync(0xffffffffu, rm0, 2));
            rm1 = fmaxf(rm1, __shfl_xor_sync(0xffffffffu, rm1, 1));
            rm1 = fmaxf(rm1, __shfl_xor_sync(0xffffffffu, rm1, 2));
            float mn0 = fmaxf(m0, rm0), mn1 = fmaxf(m1, rm1);
            float a0 = __expf(m0 - mn0), a1 = __expf(m1 - mn1);
            float rs0 = 0.f, rs1 = 0.f;
#pragma unroll
            for (int t = 0; t < 8; t++) {
                S[t][0] = __expf(S[t][0] - mn0);
                S[t][1] = __expf(S[t][1] - mn0);
                S[t][2] = __expf(S[t][2] - mn1);
                S[t][3] = __expf(S[t][3] - mn1);
                rs0 += S[t][0] + S[t][1];
                rs1 += S[t][2] + S[t][3];
            }
            rs0 += __shfl_xor_sync(0xffffffffu, rs0, 1);
            rs0 += __shfl_xor_sync(0xffffffffu, rs0, 2);
            rs1 += __shfl_xor_sync(0xffffffffu, rs1, 1);
            rs1 += __shfl_xor_sync(0xffffffffu, rs1, 2);
            l0 = l0 * a0 + rs0;
            l1 = l1 * a1 + rs1;
            m0 = mn0;
            m1 = mn1;
#pragma unroll
            for (int t = 0; t < 16; t++) {
                O[t][0] *= a0; O[t][1] *= a0;
                O[t][2] *= a1; O[t][3] *= a1;
            }

            uint32_t ph[4][4], pl[4][4];
#pragma unroll
            for (int kc2 = 0; kc2 < 4; kc2++) {
                int t0 = 2 * kc2, t1 = 2 * kc2 + 1;
                float src[8] = {S[t0][0], S[t0][1], S[t0][2], S[t0][3],
                                S[t1][0], S[t1][1], S[t1][2], S[t1][3]};
                float hv[8], lv[8];
#pragma unroll
                for (int e = 0; e < 8; e++) {
                    hv[e] = __bfloat162float(__float2bfloat16(src[e]));
                    lv[e] = src[e] - hv[e];
                }
                ph[kc2][0] = packbf(hv[0], hv[1]);
                ph[kc2][1] = packbf(hv[2], hv[3]);
                ph[kc2][2] = packbf(hv[4], hv[5]);
                ph[kc2][3] = packbf(hv[6], hv[7]);
                pl[kc2][0] = packbf(lv[0], lv[1]);
                pl[kc2][1] = packbf(lv[2], lv[3]);
                pl[kc2][2] = packbf(lv[4], lv[5]);
                pl[kc2][3] = packbf(lv[6], lv[7]);
            }

#pragma unroll
            for (int kc2 = 0; kc2 < 4; kc2++) {
#pragma unroll
                for (int p = 0; p < 8; p++) {
                    uint32_t voff = ((kc2 * 16 + frow) * STQ + p * 16 + fcol) * 2;
                    uint32_t vh[4], vl[4];
                    LDSM_X4T(vh, uVh + voff);
                    LDSM_X4T(vl, uVl + voff);
                    uint32_t bh0[2] = {vh[0], vh[1]};
                    uint32_t bh1[2] = {vh[2], vh[3]};
                    uint32_t bl0[2] = {vl[0], vl[1]};
                    uint32_t bl1[2] = {vl[2], vl[3]};
                    MMA_BF16(O[2 * p], ph[kc2], bh0);
                    MMA_BF16(O[2 * p], pl[kc2], bh0);
                    MMA_BF16(O[2 * p], ph[kc2], bl0);
                    MMA_BF16(O[2 * p + 1], ph[kc2], bh1);
                    MMA_BF16(O[2 * p + 1], pl[kc2], bh1);
                    MMA_BF16(O[2 * p + 1], ph[kc2], bl1);
                }
            }
        }
        __syncthreads();
    }

    float inv0 = 1.f / l0, inv1 = 1.f / l1;
    size_t base0 = (((size_t)b * S_ + row0) * NH_ + h) * HD_;
    size_t base1 = (((size_t)b * S_ + row1) * NH_ + h) * HD_;
#pragma unroll
    for (int t = 0; t < 16; t++) {
        int d = 8 * t + 2 * qp;
        float o0 = O[t][0] * inv0, o1 = O[t][1] * inv0;
        float o2 = O[t][2] * inv1, o3 = O[t][3] * inv1;
        float h0 = __bfloat162float(__float2bfloat16(o0));
        float h1 = __bfloat162float(__float2bfloat16(o1));
        float h2 = __bfloat162float(__float2bfloat16(o2));
        float h3 = __bfloat162float(__float2bfloat16(o3));
        *(uint32_t*)&g_ctxh[base0 + d] = packbf(h0, h1);
        *(uint32_t*)&g_ctxl[base0 + d] = packbf(o0 - h0, o1 - h1);
        *(uint32_t*)&g_ctxh[base1 + d] = packbf(h2, h3);
        *(uint32_t*)&g_ctxl[base1 + d] = packbf(o2 - h2, o3 - h3);
    }
}

// ---------------------------------------------------------------------------
extern "C" void kernel_launch(void* const* d_in, const int* in_sizes, int n_in,
                              void* d_out, int out_size) {
    (void)in_sizes; (void)n_in; (void)out_size;
    const float* x     = (const float*)d_in[0];
    const float* w_qkv = (const float*)d_in[1];
    const float* w_o   = (const float*)d_in[2];
    const float* cosT  = (const float*)d_in[3];
    const float* sinT  = (const float*)d_in[4];
    float* out = (float*)d_out;

    cudaFuncSetAttribute(attn_mma_kernel, cudaFuncAttributeMaxDynamicSharedMemorySize, ATTN_SMEM);
    cudaFuncSetAttribute(gemm_bf16_kernel<0>, cudaFuncAttributeMaxDynamicSharedMemorySize, GEMM_SMEM);
    cudaFuncSetAttribute(gemm_bf16_kernel<1>, cudaFuncAttributeMaxDynamicSharedMemorySize, GEMM_SMEM);

    bf16 *xh, *xl, *wqh, *wql, *woh, *wol, *ctxh, *ctxl;
    cudaGetSymbolAddress((void**)&xh, g_xh);
    cudaGetSymbolAddress((void**)&xl, g_xl);
    cudaGetSymbolAddress((void**)&wqh, g_wqh);
    cudaGetSymbolAddress((void**)&wql, g_wql);
    cudaGetSymbolAddress((void**)&woh, g_woh);
    cudaGetSymbolAddress((void**)&wol, g_wol);
    cudaGetSymbolAddress((void**)&ctxh, g_ctxh);
    cudaGetSymbolAddress((void**)&ctxl, g_ctxl);

    int n4x = (B_ * S_ * HID_) / 4;
    int n4q = (3 * HID_ * HID_) / 4;
    int n4o = (HID_ * HID_) / 4;
    split_kernel<<<(n4x + 255) / 256, 256>>>(x, xh, xl, n4x);
    split_kernel<<<(n4q + 255) / 256, 256>>>(w_qkv, wqh, wql, n4q);
    split_kernel<<<(n4o + 255) / 256, 256>>>(w_o, woh, wol, n4o);

    gemm_bf16_kernel<0><<<dim3(6144 / 128, 4096 / 128), 256, GEMM_SMEM>>>(xh, xl, wqh, wql, nullptr);
    rope_kernel<<<(2 * B_ * NH_ * S_ * 64) / 256, 256>>>(cosT, sinT);
    attn_mma_kernel<<<dim3(S_ / 128, B_ * NH_), 256, ATTN_SMEM>>>();
    gemm_bf16_kernel<1><<<dim3(2048 / 128, 4096 / 128), 256, GEMM_SMEM>>>(ctxh, ctxl, woh, wol, out);
}

// round 7
// speedup vs baseline: 1.0012x; 1.0012x over previous
#include <cuda_runtime.h>
#include <cuda_bf16.h>
#include <cstdint>
#include <math.h>

#define B_   2
#define S_   2048
#define HID_ 2048
#define NH_  16
#define HD_  128
#define KDIM 2048

typedef __nv_bfloat16 bf16;

// ---- persistent split buffers ----
__device__ bf16 g_xh[(size_t)B_ * S_ * HID_];
__device__ bf16 g_xl[(size_t)B_ * S_ * HID_];
__device__ bf16 g_wqh[(size_t)3 * HID_ * HID_];
__device__ bf16 g_wql[(size_t)3 * HID_ * HID_];
__device__ bf16 g_woh[(size_t)HID_ * HID_];
__device__ bf16 g_wol[(size_t)HID_ * HID_];
__device__ bf16 g_qkvh[(size_t)3 * B_ * NH_ * S_ * HD_];  // [which][b][h][s][d]
__device__ bf16 g_qkvl[(size_t)3 * B_ * NH_ * S_ * HD_];
__device__ bf16 g_ctxh[(size_t)B_ * S_ * HID_];           // [b][s][h][d]
__device__ bf16 g_ctxl[(size_t)B_ * S_ * HID_];

// ---------------- helpers ----------------
__device__ __forceinline__ uint32_t s2u(const void* p) {
    return (uint32_t)__cvta_generic_to_shared(p);
}
__device__ __forceinline__ uint32_t packbf(float lo, float hi) {
    uint32_t r;
    asm("cvt.rn.bf16x2.f32 %0, %1, %2;" : "=r"(r) : "f"(hi), "f"(lo));
    return r;
}

#define MMA_BF16(d, a, b)                                                     \
    asm volatile(                                                             \
        "mma.sync.aligned.m16n8k16.row.col.f32.bf16.bf16.f32 "                \
        "{%0,%1,%2,%3}, {%4,%5,%6,%7}, {%8,%9}, {%0,%1,%2,%3};\n"             \
        : "+f"((d)[0]), "+f"((d)[1]), "+f"((d)[2]), "+f"((d)[3])              \
        : "r"((a)[0]), "r"((a)[1]), "r"((a)[2]), "r"((a)[3]),                 \
          "r"((b)[0]), "r"((b)[1]))

#define LDSM_X4(r, addr)                                                      \
    asm volatile("ldmatrix.sync.aligned.m8n8.x4.shared.b16 {%0,%1,%2,%3}, [%4];" \
                 : "=r"((r)[0]), "=r"((r)[1]), "=r"((r)[2]), "=r"((r)[3])     \
                 : "r"(addr))

#define LDSM_X4T(r, addr)                                                     \
    asm volatile("ldmatrix.sync.aligned.m8n8.x4.trans.shared.b16 {%0,%1,%2,%3}, [%4];" \
                 : "=r"((r)[0]), "=r"((r)[1]), "=r"((r)[2]), "=r"((r)[3])     \
                 : "r"(addr))

#define CP_ASYNC16(dst, src)                                                  \
    asm volatile("cp.async.cg.shared.global [%0], [%1], 16;" ::               \
                 "r"(dst), "l"(src))
#define CP_COMMIT() asm volatile("cp.async.commit_group;" ::: "memory")
#define CP_WAIT1()  asm volatile("cp.async.wait_group 1;" ::: "memory")

// ---------------------------------------------------------------------------
// Split fp32 -> bf16 hi/lo (prep).
// ---------------------------------------------------------------------------
__global__ __launch_bounds__(256)
void split_kernel(const float* __restrict__ src, bf16* __restrict__ h,
                  bf16* __restrict__ l, int n4) {
    int i = blockIdx.x * 256 + threadIdx.x;
    if (i >= n4) return;
    float4 v = *(const float4*)&src[(size_t)i * 4];
    float f[4] = {v.x, v.y, v.z, v.w};
    float hf[4], lf[4];
#pragma unroll
    for (int e = 0; e < 4; e++) {
        hf[e] = __bfloat162float(__float2bfloat16(f[e]));
        lf[e] = f[e] - hf[e];
    }
    *(uint2*)&h[(size_t)i * 4] = make_uint2(packbf(hf[0], hf[1]), packbf(hf[2], hf[3]));
    *(uint2*)&l[(size_t)i * 4] = make_uint2(packbf(lf[0], lf[1]), packbf(lf[2], lf[3]));
}

// ---------------------------------------------------------------------------
// Pipelined split-bf16 GEMM: C[m][n] = sum_k A[m][k]*W[n][k]
// BM=BN=128, BK=16/stage, 2-stage cp.async double buffer, 256 thr, 8 warps.
// smem: 2 stages x 4 arrays x [128][24] bf16 = 49152 B  -> 2 CTAs/SM.
// MODE 0: scatter split bf16 into g_qkvh/g_qkvl.  MODE 1: fp32 out.
// ---------------------------------------------------------------------------
#define GST 24                       // row stride (16 + 8 pad)
#define ARRE (128 * GST)             // elems per array
#define STAGEE (4 * ARRE)            // elems per stage
#define GEMM_SMEM (2 * STAGEE * 2)   // bytes = 49152

template <int MODE>
__global__ __launch_bounds__(256, 2)
void gemm_bf16_kernel(const bf16* __restrict__ Agh, const bf16* __restrict__ Agl,
                      const bf16* __restrict__ Bgh, const bf16* __restrict__ Bgl,
                      float* __restrict__ Cout) {
    extern __shared__ bf16 smem[];
    const int m0 = blockIdx.y * 128;
    const int n0 = blockIdx.x * 128;
    const int tid = threadIdx.x;
    const int lane = tid & 31;
    const int warp = tid >> 5;
    const int warpM = warp & 3;
    const int warpN = warp >> 2;

    const uint32_t sbase = s2u(smem);
    const int g = lane >> 2;
    const int qp = lane & 3;
    const int frow = lane & 15;
    const int fcol = (lane >> 4) << 3;

    // per-thread load slot: row = tid>>1 (0..127), half = tid&1 (8 elems)
    const int lrow = tid >> 1;
    const int lhalf = tid & 1;
    const size_t gaoff = (size_t)(m0 + lrow) * KDIM + lhalf * 8;
    const size_t gboff = (size_t)(n0 + lrow) * KDIM + lhalf * 8;
    const uint32_t dstoff = (lrow * GST + lhalf * 8) * 2;

    float C[2][8][4];
#pragma unroll
    for (int mt = 0; mt < 2; mt++)
#pragma unroll
        for (int nt = 0; nt < 8; nt++)
#pragma unroll
            for (int r = 0; r < 4; r++) C[mt][nt][r] = 0.f;

#define ISSUE(s)                                                              \
    do {                                                                      \
        int buf_ = (s) & 1;                                                   \
        int k0_ = (s) * 16;                                                   \
        uint32_t d_ = sbase + buf_ * (STAGEE * 2) + dstoff;                   \
        CP_ASYNC16(d_,                Agh + gaoff + k0_);                     \
        CP_ASYNC16(d_ + ARRE * 2,     Agl + gaoff + k0_);                     \
        CP_ASYNC16(d_ + ARRE * 4,     Bgh + gboff + k0_);                     \
        CP_ASYNC16(d_ + ARRE * 6,     Bgl + gboff + k0_);                     \
        CP_COMMIT();                                                          \
    } while (0)

    ISSUE(0);
    ISSUE(1);

    const int NSTAGES = KDIM / 16;   // 128
#pragma unroll 1
    for (int s = 0; s < NSTAGES; s++) {
        CP_WAIT1();
        __syncthreads();

        const int buf = s & 1;
        const uint32_t uAh = sbase + buf * (STAGEE * 2);
        const uint32_t uAl = uAh + ARRE * 2;
        const uint32_t uBh = uAh + ARRE * 4;
        const uint32_t uBl = uAh + ARRE * 6;

        uint32_t a_hi[2][4], a_lo[2][4];
#pragma unroll
        for (int mt = 0; mt < 2; mt++) {
            uint32_t off = ((warpM * 32 + mt * 16 + frow) * GST + fcol) * 2;
            LDSM_X4(a_hi[mt], uAh + off);
            LDSM_X4(a_lo[mt], uAl + off);
        }
#pragma unroll
        for (int p = 0; p < 4; p++) {
            uint32_t off = ((warpN * 64 + p * 16 + frow) * GST + fcol) * 2;
            uint32_t kb_h[4], kb_l[4];
            LDSM_X4(kb_h, uBh + off);
            LDSM_X4(kb_l, uBl + off);
            uint32_t bh0[2] = {kb_h[0], kb_h[2]};
            uint32_t bh1[2] = {kb_h[1], kb_h[3]};
            uint32_t bl0[2] = {kb_l[0], kb_l[2]};
            uint32_t bl1[2] = {kb_l[1], kb_l[3]};
#pragma unroll
            for (int mt = 0; mt < 2; mt++) {
                MMA_BF16(C[mt][2 * p], a_hi[mt], bh0);
                MMA_BF16(C[mt][2 * p], a_lo[mt], bh0);
                MMA_BF16(C[mt][2 * p], a_hi[mt], bl0);
                MMA_BF16(C[mt][2 * p + 1], a_hi[mt], bh1);
                MMA_BF16(C[mt][2 * p + 1], a_lo[mt], bh1);
                MMA_BF16(C[mt][2 * p + 1], a_hi[mt], bl1);
            }
        }
        __syncthreads();
        if (s + 2 < NSTAGES) ISSUE(s + 2);
    }
#undef ISSUE

    // epilogue
#pragma unroll
    for (int mt = 0; mt < 2; mt++) {
#pragma unroll
        for (int nt = 0; nt < 8; nt++) {
            int gm0 = m0 + warpM * 32 + mt * 16 + g;
            int gn = n0 + warpN * 64 + nt * 8 + qp * 2;
            if (MODE == 0) {
                int which = gn >> 11;
                int rem = gn & 2047;
                int h = rem >> 7;
                int d = rem & 127;
#pragma unroll
                for (int rr = 0; rr < 2; rr++) {
                    int gm = gm0 + rr * 8;
                    int b = gm >> 11;
                    int s2 = gm & 2047;
                    size_t off = (size_t)which * ((size_t)B_ * NH_ * S_ * HD_) +
                                 (((size_t)(b * NH_ + h)) * S_ + s2) * HD_ + d;
                    float v0 = C[mt][nt][rr * 2], v1 = C[mt][nt][rr * 2 + 1];
                    float h0 = __bfloat162float(__float2bfloat16(v0));
                    float h1 = __bfloat162float(__float2bfloat16(v1));
                    *(uint32_t*)&g_qkvh[off] = packbf(h0, h1);
                    *(uint32_t*)&g_qkvl[off] = packbf(v0 - h0, v1 - h1);
                }
            } else {
                *(float2*)&Cout[(size_t)gm0 * HID_ + gn] =
                    make_float2(C[mt][nt][0], C[mt][nt][1]);
                *(float2*)&Cout[(size_t)(gm0 + 8) * HID_ + gn] =
                    make_float2(C[mt][nt][2], C[mt][nt][3]);
            }
        }
    }
}

// ---------------------------------------------------------------------------
// RoPE in-place on split Q and K halves.
// ---------------------------------------------------------------------------
__global__ __launch_bounds__(256)
void rope_kernel(const float* __restrict__ cosT, const float* __restrict__ sinT) {
    long long t = (long long)blockIdx.x * 256 + threadIdx.x;
    int d = (int)(t & 63);
    long long row = t >> 6;
    int s = (int)(row % S_);
    bf16* ph = g_qkvh + row * HD_;
    bf16* pl = g_qkvl + row * HD_;
    float x1 = __bfloat162float(ph[d]) + __bfloat162float(pl[d]);
    float x2 = __bfloat162float(ph[d + 64]) + __bfloat162float(pl[d + 64]);
    float c1 = cosT[s * HD_ + d];
    float s1 = sinT[s * HD_ + d];
    float c2 = cosT[s * HD_ + d + 64];
    float s2 = sinT[s * HD_ + d + 64];
    float r1 = x1 * c1 - x2 * s1;
    float r2 = x2 * c2 + x1 * s2;
    float h1 = __bfloat162float(__float2bfloat16(r1));
    float h2 = __bfloat162float(__float2bfloat16(r2));
    ph[d] = __float2bfloat16(h1);
    pl[d] = __float2bfloat16(r1 - h1);
    ph[d + 64] = __float2bfloat16(h2);
    pl[d + 64] = __float2bfloat16(r2 - h2);
}

// ---------------------------------------------------------------------------
// Split-bf16 tensor-core causal flash attention. BQ=128, BK=64, 256 threads.
// ---------------------------------------------------------------------------
#define STQ 136
#define ATTN_SMEM ((2 * 128 + 4 * 64) * STQ * 2)

__global__ __launch_bounds__(256, 1)
void attn_mma_kernel() {
    extern __shared__ char smraw[];
    bf16* sQh = (bf16*)smraw;
    bf16* sQl = sQh + 128 * STQ;
    bf16* sKh = sQl + 128 * STQ;
    bf16* sKl = sKh + 64 * STQ;
    bf16* sVh = sKl + 64 * STQ;
    bf16* sVl = sVh + 64 * STQ;

    const int tid = threadIdx.x;
    const int lane = tid & 31;
    const int w = tid >> 5;
    const int qp = lane & 3;
    const int g = lane >> 2;
    const int frow = lane & 15;
    const int fcol = (lane >> 4) << 3;

    const int qt = blockIdx.x;
    const int bh = blockIdx.y;
    const int b = bh >> 4;
    const int h = bh & 15;
    const int q0 = qt * 128;

    const size_t hs = (size_t)S_ * HD_;
    const bf16* Qh = g_qkvh + (size_t)bh * hs;
    const bf16* Ql = g_qkvl + (size_t)bh * hs;
    const bf16* Kh = g_qkvh + (size_t)(B_ * NH_ + bh) * hs;
    const bf16* Kl = g_qkvl + (size_t)(B_ * NH_ + bh) * hs;
    const bf16* Vh = g_qkvh + (size_t)(2 * B_ * NH_ + bh) * hs;
    const bf16* Vl = g_qkvl + (size_t)(2 * B_ * NH_ + bh) * hs;

#pragma unroll
    for (int i = 0; i < 8; i++) {
        int idx = tid + i * 256;
        int r = idx >> 4;
        int d = (idx & 15) * 8;
        size_t ga = (size_t)(q0 + r) * HD_ + d;
        *(uint4*)&sQh[r * STQ + d] = *(const uint4*)&Qh[ga];
        *(uint4*)&sQl[r * STQ + d] = *(const uint4*)&Ql[ga];
    }

    const uint32_t uQh = s2u(sQh), uQl = s2u(sQl);
    const uint32_t uKh = s2u(sKh), uKl = s2u(sKl);
    const uint32_t uVh = s2u(sVh), uVl = s2u(sVl);

    float O[16][4];
#pragma unroll
    for (int t = 0; t < 16; t++)
#pragma unroll
        for (int r = 0; r < 4; r++) O[t][r] = 0.f;
    float m0 = -1e30f, m1 = -1e30f, l0 = 0.f, l1 = 0.f;

    const float sc = 0.08838834764831845f;
    const int row0 = q0 + w * 16 + g;
    const int row1 = row0 + 8;

    __syncthreads();

    const int ktn = (q0 + 128) >> 6;
    for (int kt = 0; kt < ktn; kt++) {
        const int k0 = kt * 64;
#pragma unroll
        for (int i = 0; i < 4; i++) {
            int idx = tid + i * 256;
            int r = idx >> 4;
            int d = (idx & 15) * 8;
            size_t ga = (size_t)(k0 + r) * HD_ + d;
            *(uint4*)&sKh[r * STQ + d] = *(const uint4*)&Kh[ga];
            *(uint4*)&sKl[r * STQ + d] = *(const uint4*)&Kl[ga];
            *(uint4*)&sVh[r * STQ + d] = *(const uint4*)&Vh[ga];
            *(uint4*)&sVl[r * STQ + d] = *(const uint4*)&Vl[ga];
        }
        __syncthreads();

        const bool active = (k0 <= q0 + w * 16 + 15);
        if (active) {
            float S[8][4];
#pragma unroll
            for (int t = 0; t < 8; t++)
#pragma unroll
                for (int r = 0; r < 4; r++) S[t][r] = 0.f;

#pragma unroll
            for (int kc = 0; kc < 8; kc++) {
                const int col = kc * 16 + fcol;
                uint32_t qh[4], ql[4];
                uint32_t qoff = ((w * 16 + frow) * STQ + col) * 2;
                LDSM_X4(qh, uQh + qoff);
                LDSM_X4(ql, uQl + qoff);
#pragma unroll
                for (int p = 0; p < 4; p++) {
                    uint32_t koff = ((p * 16 + frow) * STQ + col) * 2;
                    uint32_t kh[4], kl[4];
                    LDSM_X4(kh, uKh + koff);
                    LDSM_X4(kl, uKl + koff);
                    uint32_t bh0[2] = {kh[0], kh[2]};
                    uint32_t bh1[2] = {kh[1], kh[3]};
                    uint32_t bl0[2] = {kl[0], kl[2]};
                    uint32_t bl1[2] = {kl[1], kl[3]};
                    MMA_BF16(S[2 * p], qh, bh0);
                    MMA_BF16(S[2 * p], ql, bh0);
                    MMA_BF16(S[2 * p], qh, bl0);
                    MMA_BF16(S[2 * p + 1], qh, bh1);
                    MMA_BF16(S[2 * p + 1], ql, bh1);
                    MMA_BF16(S[2 * p + 1], qh, bl1);
                }
            }

            const bool maskneed = (k0 + 63 > row0);
#pragma unroll
            for (int t = 0; t < 8; t++) {
                int c0 = k0 + 8 * t + 2 * qp;
#pragma unroll
                for (int r = 0; r < 4; r++) {
                    S[t][r] *= sc;
                    if (maskneed) {
                        int colg = c0 + (r & 1);
                        int rowg = (r < 2) ? row0 : row1;
                        if (colg > rowg) S[t][r] = -1e9f;
                    }
                }
            }

            float rm0 = -1e30f, rm1 = -1e30f;
#pragma unroll
            for (int t = 0; t < 8; t++) {
                rm0 = fmaxf(rm0, fmaxf(S[t][0], S[t][1]));
                rm1 = fmaxf(rm1, fmaxf(S[t][2], S[t][3]));
            }
            rm0 = fmaxf(rm0, __shfl_xor_sync(0xffffffffu, rm0, 1));
            rm0 = fmaxf(rm0, __shfl_xor_sync(0xffffffffu, rm0, 2));
            rm1 = fmaxf(rm1, __shfl_xor_sync(0xffffffffu, rm1, 1));
            rm1 = fmaxf(rm1, __shfl_xor_sync(0xffffffffu, rm1, 2));
            float mn0 = fmaxf(m0, rm0), mn1 = fmaxf(m1, rm1);
            float a0 = __expf(m0 - mn0), a1 = __expf(m1 - mn1);
            float rs0 = 0.f, rs1 = 0.f;
#pragma unroll
            for (int t = 0; t < 8; t++) {
                S[t][0] = __expf(S[t][0] - mn0);
                S[t][1] = __expf(S[t][1] - mn0);
                S[t][2] = __expf(S[t][2] - mn1);
                S[t][3] = __expf(S[t][3] - mn1);
                rs0 += S[t][0] + S[t][1];
                rs1 += S[t][2] + S[t][3];
            }
            rs0 += __shfl_xor_sync(0xffffffffu, rs0, 1);
            rs0 += __shfl_xor_sync(0xffffffffu, rs0, 2);
            rs1 += __shfl_xor_sync(0xffffffffu, rs1, 1);
            rs1 += __shfl_xor_sync(0xffffffffu, rs1, 2);
            l0 = l0 * a0 + rs0;
            l1 = l1 * a1 + rs1;
            m0 = mn0;
            m1 = mn1;
#pragma unroll
            for (int t = 0; t < 16; t++) {
                O[t][0] *= a0; O[t][1] *= a0;
                O[t][2] *= a1; O[t][3] *= a1;
            }

            uint32_t ph[4][4], pl[4][4];
#pragma unroll
            for (int kc2 = 0; kc2 < 4; kc2++) {
                int t0 = 2 * kc2, t1 = 2 * kc2 + 1;
                float src[8] = {S[t0][0], S[t0][1], S[t0][2], S[t0][3],
                                S[t1][0], S[t1][1], S[t1][2], S[t1][3]};
                float hv[8], lv[8];
#pragma unroll
                for (int e = 0; e < 8; e++) {
                    hv[e] = __bfloat162float(__float2bfloat16(src[e]));
                    lv[e] = src[e] - hv[e];
                }
                ph[kc2][0] = packbf(hv[0], hv[1]);
                ph[kc2][1] = packbf(hv[2], hv[3]);
                ph[kc2][2] = packbf(hv[4], hv[5]);
                ph[kc2][3] = packbf(hv[6], hv[7]);
                pl[kc2][0] = packbf(lv[0], lv[1]);
                pl[kc2][1] = packbf(lv[2], lv[3]);
                pl[kc2][2] = packbf(lv[4], lv[5]);
                pl[kc2][3] = packbf(lv[6], lv[7]);
            }

#pragma unroll
            for (int kc2 = 0; kc2 < 4; kc2++) {
#pragma unroll
                for (int p = 0; p < 8; p++) {
                    uint32_t voff = ((kc2 * 16 + frow) * STQ + p * 16 + fcol) * 2;
                    uint32_t vh[4], vl[4];
                    LDSM_X4T(vh, uVh + voff);
                    LDSM_X4T(vl, uVl + voff);
                    uint32_t bh0[2] = {vh[0], vh[1]};
                    uint32_t bh1[2] = {vh[2], vh[3]};
                    uint32_t bl0[2] = {vl[0], vl[1]};
                    uint32_t bl1[2] = {vl[2], vl[3]};
                    MMA_BF16(O[2 * p], ph[kc2], bh0);
                    MMA_BF16(O[2 * p], pl[kc2], bh0);
                    MMA_BF16(O[2 * p], ph[kc2], bl0);
                    MMA_BF16(O[2 * p + 1], ph[kc2], bh1);
                    MMA_BF16(O[2 * p + 1], pl[kc2], bh1);
                    MMA_BF16(O[2 * p + 1], ph[kc2], bl1);
                }
            }
        }
        __syncthreads();
    }

    float inv0 = 1.f / l0, inv1 = 1.f / l1;
    size_t base0 = (((size_t)b * S_ + row0) * NH_ + h) * HD_;
    size_t base1 = (((size_t)b * S_ + row1) * NH_ + h) * HD_;
#pragma unroll
    for (int t = 0; t < 16; t++) {
        int d = 8 * t + 2 * qp;
        float o0 = O[t][0] * inv0, o1 = O[t][1] * inv0;
        float o2 = O[t][2] * inv1, o3 = O[t][3] * inv1;
        float h0 = __bfloat162float(__float2bfloat16(o0));
        float h1 = __bfloat162float(__float2bfloat16(o1));
        float h2 = __bfloat162float(__float2bfloat16(o2));
        float h3 = __bfloat162float(__float2bfloat16(o3));
        *(uint32_t*)&g_ctxh[base0 + d] = packbf(h0, h1);
        *(uint32_t*)&g_ctxl[base0 + d] = packbf(o0 - h0, o1 - h1);
        *(uint32_t*)&g_ctxh[base1 + d] = packbf(h2, h3);
        *(uint32_t*)&g_ctxl[base1 + d] = packbf(o2 - h2, o3 - h3);
    }
}

// ---------------------------------------------------------------------------
extern "C" void kernel_launch(void* const* d_in, const int* in_sizes, int n_in,
                              void* d_out, int out_size) {
    (void)in_sizes; (void)n_in; (void)out_size;
    const float* x     = (const float*)d_in[0];
    const float* w_qkv = (const float*)d_in[1];
    const float* w_o   = (const float*)d_in[2];
    const float* cosT  = (const float*)d_in[3];
    const float* sinT  = (const float*)d_in[4];
    float* out = (float*)d_out;

    cudaFuncSetAttribute(attn_mma_kernel, cudaFuncAttributeMaxDynamicSharedMemorySize, ATTN_SMEM);
    cudaFuncSetAttribute(gemm_bf16_kernel<0>, cudaFuncAttributeMaxDynamicSharedMemorySize, GEMM_SMEM);
    cudaFuncSetAttribute(gemm_bf16_kernel<1>, cudaFuncAttributeMaxDynamicSharedMemorySize, GEMM_SMEM);

    bf16 *xh, *xl, *wqh, *wql, *woh, *wol, *ctxh, *ctxl;
    cudaGetSymbolAddress((void**)&xh, g_xh);
    cudaGetSymbolAddress((void**)&xl, g_xl);
    cudaGetSymbolAddress((void**)&wqh, g_wqh);
    cudaGetSymbolAddress((void**)&wql, g_wql);
    cudaGetSymbolAddress((void**)&woh, g_woh);
    cudaGetSymbolAddress((void**)&wol, g_wol);
    cudaGetSymbolAddress((void**)&ctxh, g_ctxh);
    cudaGetSymbolAddress((void**)&ctxl, g_ctxl);

    int n4x = (B_ * S_ * HID_) / 4;
    int n4q = (3 * HID_ * HID_) / 4;
    int n4o = (HID_ * HID_) / 4;
    split_kernel<<<(n4x + 255) / 256, 256>>>(x, xh, xl, n4x);
    split_kernel<<<(n4q + 255) / 256, 256>>>(w_qkv, wqh, wql, n4q);
    split_kernel<<<(n4o + 255) / 256, 256>>>(w_o, woh, wol, n4o);

    gemm_bf16_kernel<0><<<dim3(6144 / 128, 4096 / 128), 256, GEMM_SMEM>>>(xh, xl, wqh, wql, nullptr);
    rope_kernel<<<(2 * B_ * NH_ * S_ * 64) / 256, 256>>>(cosT, sinT);
    attn_mma_kernel<<<dim3(S_ / 128, B_ * NH_), 256, ATTN_SMEM>>>();
    gemm_bf16_kernel<1><<<dim3(2048 / 128, 4096 / 128), 256, GEMM_SMEM>>>(ctxh, ctxl, woh, wol, out);
}

// round 9
// speedup vs baseline: 1.0592x; 1.0580x over previous
#include <cuda_runtime.h>
#include <cuda_bf16.h>
#include <cstdint>
#include <math.h>

#define B_   2
#define S_   2048
#define HID_ 2048
#define NH_  16
#define HD_  128
#define KDIM 2048

__device__ float g_qkv[(size_t)3 * B_ * NH_ * S_ * HD_];   // [which][b][h][s][d]
__device__ float g_ctx[(size_t)B_ * S_ * HID_];            // [b][s][h][d] row-major [M][2048]

// ---------------- helpers ----------------
__device__ __forceinline__ uint32_t s2u(const void* p) {
    return (uint32_t)__cvta_generic_to_shared(p);
}
__device__ __forceinline__ uint32_t packbf(float lo, float hi) {
    uint32_t r;
    asm("cvt.rn.bf16x2.f32 %0, %1, %2;" : "=r"(r) : "f"(hi), "f"(lo));
    return r;
}

#define MMA_BF16(d, a, b)                                                     \
    asm volatile(                                                             \
        "mma.sync.aligned.m16n8k16.row.col.f32.bf16.bf16.f32 "                \
        "{%0,%1,%2,%3}, {%4,%5,%6,%7}, {%8,%9}, {%0,%1,%2,%3};\n"             \
        : "+f"((d)[0]), "+f"((d)[1]), "+f"((d)[2]), "+f"((d)[3])              \
        : "r"((a)[0]), "r"((a)[1]), "r"((a)[2]), "r"((a)[3]),                 \
          "r"((b)[0]), "r"((b)[1]))

#define LDSM_X4(r, addr)                                                      \
    asm volatile("ldmatrix.sync.aligned.m8n8.x4.shared.b16 {%0,%1,%2,%3}, [%4];" \
                 : "=r"((r)[0]), "=r"((r)[1]), "=r"((r)[2]), "=r"((r)[3])     \
                 : "r"(addr))

#define LDSM_X4T(r, addr)                                                     \
    asm volatile("ldmatrix.sync.aligned.m8n8.x4.trans.shared.b16 {%0,%1,%2,%3}, [%4];" \
                 : "=r"((r)[0]), "=r"((r)[1]), "=r"((r)[2]), "=r"((r)[3])     \
                 : "r"(addr))

// ---------------------------------------------------------------------------
// Split-bf16 tensor-core GEMM, warp tile 64x32 (smem-BW balanced).
// C[m][n] = sum_k A[m][k]*W[n][k]. BM=BN=128, BK=32, 256 thr,
// 8 warps = 2 warpM (64 rows) x 4 warpN (32 cols).
// Per k16: 8 A-LDSM + 4 B-LDSM for 48 MMAs (vs 12 LDSM / 24 MMA before).
// MODE 0: A = x, scatter q/k/v into g_qkv.  MODE 1: A = g_ctx, write Cout.
// ---------------------------------------------------------------------------
#define SMSTRIDE 40

template <int MODE>
__global__ __launch_bounds__(256, 2)
void gemm_bf16_kernel(const float* __restrict__ Ain,
                      const float* __restrict__ W,
                      float* __restrict__ Cout) {
    const int m0 = blockIdx.y * 128;
    const int n0 = blockIdx.x * 128;
    const int tid = threadIdx.x;
    const int lane = tid & 31;
    const int warp = tid >> 5;
    const int warpM = warp & 1;    // 0..1 -> 64 rows each
    const int warpN = warp >> 1;   // 0..3 -> 32 cols each

    const float* A = (MODE == 0) ? Ain : g_ctx;

    __shared__ __nv_bfloat16 Ah[128 * SMSTRIDE];
    __shared__ __nv_bfloat16 Al[128 * SMSTRIDE];
    __shared__ __nv_bfloat16 Bh[128 * SMSTRIDE];
    __shared__ __nv_bfloat16 Bl[128 * SMSTRIDE];

    float C[4][4][4];
#pragma unroll
    for (int mt = 0; mt < 4; mt++)
#pragma unroll
        for (int nt = 0; nt < 4; nt++)
#pragma unroll
            for (int r = 0; r < 4; r++) C[mt][nt][r] = 0.f;

    const uint32_t uAh = s2u(Ah), uAl = s2u(Al), uBh = s2u(Bh), uBl = s2u(Bl);
    const int g = lane >> 2;
    const int qp = lane & 3;
    const int frow = lane & 15;
    const int fcol = (lane >> 4) << 3;

    for (int k0 = 0; k0 < KDIM; k0 += 32) {
        // ---- load fp32 tiles, split into hi/lo bf16, store to smem ----
#pragma unroll
        for (int t = 0; t < 4; t++) {
            int l = tid + t * 256;
            int row = l >> 3;
            int kc = (l & 7) * 4;
            float4 av = *(const float4*)&A[(size_t)(m0 + row) * KDIM + k0 + kc];
            float4 bv = *(const float4*)&W[(size_t)(n0 + row) * KDIM + k0 + kc];
            float af[4] = {av.x, av.y, av.z, av.w};
            float bf[4] = {bv.x, bv.y, bv.z, bv.w};
            float ahf[4], alf[4], bhf[4], blf[4];
#pragma unroll
            for (int e = 0; e < 4; e++) {
                ahf[e] = __bfloat162float(__float2bfloat16(af[e]));
                alf[e] = af[e] - ahf[e];
                bhf[e] = __bfloat162float(__float2bfloat16(bf[e]));
                blf[e] = bf[e] - bhf[e];
            }
            uint32_t* pAh = (uint32_t*)&Ah[row * SMSTRIDE + kc];
            uint32_t* pAl = (uint32_t*)&Al[row * SMSTRIDE + kc];
            uint32_t* pBh = (uint32_t*)&Bh[row * SMSTRIDE + kc];
            uint32_t* pBl = (uint32_t*)&Bl[row * SMSTRIDE + kc];
            pAh[0] = packbf(ahf[0], ahf[1]); pAh[1] = packbf(ahf[2], ahf[3]);
            pAl[0] = packbf(alf[0], alf[1]); pAl[1] = packbf(alf[2], alf[3]);
            pBh[0] = packbf(bhf[0], bhf[1]); pBh[1] = packbf(bhf[2], bhf[3]);
            pBl[0] = packbf(blf[0], blf[1]); pBl[1] = packbf(blf[2], blf[3]);
        }
        __syncthreads();

#pragma unroll
        for (int kc = 0; kc < 2; kc++) {
            const int col = kc * 16 + fcol;
            uint32_t a_hi[4][4], a_lo[4][4];
#pragma unroll
            for (int mt = 0; mt < 4; mt++) {
                uint32_t off = ((warpM * 64 + mt * 16 + frow) * SMSTRIDE + col) * 2;
                LDSM_X4(a_hi[mt], uAh + off);
                LDSM_X4(a_lo[mt], uAl + off);
            }
#pragma unroll
            for (int p = 0; p < 2; p++) {
                uint32_t off = ((warpN * 32 + p * 16 + frow) * SMSTRIDE + col) * 2;
                uint32_t kb_h[4], kb_l[4];
                LDSM_X4(kb_h, uBh + off);
                LDSM_X4(kb_l, uBl + off);
                uint32_t bh0[2] = {kb_h[0], kb_h[2]};
                uint32_t bh1[2] = {kb_h[1], kb_h[3]};
                uint32_t bl0[2] = {kb_l[0], kb_l[2]};
                uint32_t bl1[2] = {kb_l[1], kb_l[3]};
                // pass hh: 8 independent accumulators
#pragma unroll
                for (int mt = 0; mt < 4; mt++) MMA_BF16(C[mt][2 * p], a_hi[mt], bh0);
#pragma unroll
                for (int mt = 0; mt < 4; mt++) MMA_BF16(C[mt][2 * p + 1], a_hi[mt], bh1);
                // pass lh
#pragma unroll
                for (int mt = 0; mt < 4; mt++) MMA_BF16(C[mt][2 * p], a_lo[mt], bh0);
#pragma unroll
                for (int mt = 0; mt < 4; mt++) MMA_BF16(C[mt][2 * p + 1], a_lo[mt], bh1);
                // pass hl
#pragma unroll
                for (int mt = 0; mt < 4; mt++) MMA_BF16(C[mt][2 * p], a_hi[mt], bl0);
#pragma unroll
                for (int mt = 0; mt < 4; mt++) MMA_BF16(C[mt][2 * p + 1], a_hi[mt], bl1);
            }
        }
        __syncthreads();
    }

    // ---- epilogue ----
#pragma unroll
    for (int mt = 0; mt < 4; mt++) {
#pragma unroll
        for (int nt = 0; nt < 4; nt++) {
            int gm0 = m0 + warpM * 64 + mt * 16 + g;
            int gn = n0 + warpN * 32 + nt * 8 + qp * 2;
            float2 v0 = make_float2(C[mt][nt][0], C[mt][nt][1]);
            float2 v1 = make_float2(C[mt][nt][2], C[mt][nt][3]);
            if (MODE == 0) {
                int which = gn >> 11;
                int rem = gn & 2047;
                int h = rem >> 7;
                int d = rem & 127;
#pragma unroll
                for (int rr = 0; rr < 2; rr++) {
                    int gm = gm0 + rr * 8;
                    int b = gm >> 11;
                    int s = gm & 2047;
                    size_t off = (size_t)which * ((size_t)B_ * NH_ * S_ * HD_) +
                                 (((size_t)(b * NH_ + h)) * S_ + s) * HD_ + d;
                    *(float2*)&g_qkv[off] = rr ? v1 : v0;
                }
            } else {
                *(float2*)&Cout[(size_t)gm0 * HID_ + gn] = v0;
                *(float2*)&Cout[(size_t)(gm0 + 8) * HID_ + gn] = v1;
            }
        }
    }
}

// ---------------------------------------------------------------------------
// RoPE in-place on Q and K halves of g_qkv.
// ---------------------------------------------------------------------------
__global__ __launch_bounds__(256)
void rope_kernel(const float* __restrict__ cosT, const float* __restrict__ sinT) {
    long long t = (long long)blockIdx.x * 256 + threadIdx.x;
    int d = (int)(t & 63);
    long long row = t >> 6;
    int s = (int)(row % S_);
    float* p = g_qkv + row * HD_;
    float x1 = p[d];
    float x2 = p[d + 64];
    float c1 = cosT[s * HD_ + d];
    float s1 = sinT[s * HD_ + d];
    float c2 = cosT[s * HD_ + d + 64];
    float s2 = sinT[s * HD_ + d + 64];
    p[d]      = x1 * c1 - x2 * s1;
    p[d + 64] = x2 * c2 + x1 * s2;
}

// ---------------------------------------------------------------------------
// Split-bf16 tensor-core causal flash attention. BQ=128, BK=64, 256 threads.
// (round-4 structure; MMA issue reordered to alternate accumulators)
// ---------------------------------------------------------------------------
#define STQ 136
#define ATTN_SMEM ((2 * 128 + 4 * 64) * STQ * 2)

__global__ __launch_bounds__(256, 1)
void attn_mma_kernel() {
    extern __shared__ char smraw[];
    __nv_bfloat16* sQh = (__nv_bfloat16*)smraw;
    __nv_bfloat16* sQl = sQh + 128 * STQ;
    __nv_bfloat16* sKh = sQl + 128 * STQ;
    __nv_bfloat16* sKl = sKh + 64 * STQ;
    __nv_bfloat16* sVh = sKl + 64 * STQ;
    __nv_bfloat16* sVl = sVh + 64 * STQ;

    const int tid = threadIdx.x;
    const int lane = tid & 31;
    const int w = tid >> 5;
    const int qp = lane & 3;
    const int g = lane >> 2;
    const int frow = lane & 15;
    const int fcol = (lane >> 4) << 3;

    const int qt = blockIdx.x;
    const int bh = blockIdx.y;
    const int b = bh >> 4;
    const int h = bh & 15;
    const int q0 = qt * 128;

    const size_t hs = (size_t)S_ * HD_;
    const float* Qg = g_qkv + (size_t)bh * hs;
    const float* Kg = g_qkv + (size_t)(B_ * NH_ + bh) * hs;
    const float* Vg = g_qkv + (size_t)(2 * B_ * NH_ + bh) * hs;

    // ---- load Q tile (128 x 128), split to hi/lo bf16 ----
#pragma unroll
    for (int i = 0; i < 16; i++) {
        int idx = tid + i * 256;
        int r = idx >> 5;
        int d = (idx & 31) << 2;
        float4 v = *(const float4*)&Qg[(size_t)(q0 + r) * HD_ + d];
        float f[4] = {v.x, v.y, v.z, v.w};
        float hf[4], lf[4];
#pragma unroll
        for (int e = 0; e < 4; e++) {
            hf[e] = __bfloat162float(__float2bfloat16(f[e]));
            lf[e] = f[e] - hf[e];
        }
        uint32_t* ph = (uint32_t*)&sQh[r * STQ + d];
        uint32_t* pl = (uint32_t*)&sQl[r * STQ + d];
        ph[0] = packbf(hf[0], hf[1]); ph[1] = packbf(hf[2], hf[3]);
        pl[0] = packbf(lf[0], lf[1]); pl[1] = packbf(lf[2], lf[3]);
    }

    const uint32_t uQh = s2u(sQh), uQl = s2u(sQl);
    const uint32_t uKh = s2u(sKh), uKl = s2u(sKl);
    const uint32_t uVh = s2u(sVh), uVl = s2u(sVl);

    float O[16][4];
#pragma unroll
    for (int t = 0; t < 16; t++)
#pragma unroll
        for (int r = 0; r < 4; r++) O[t][r] = 0.f;
    float m0 = -1e30f, m1 = -1e30f, l0 = 0.f, l1 = 0.f;

    const float sc = 0.08838834764831845f;
    const int row0 = q0 + w * 16 + g;
    const int row1 = row0 + 8;

    __syncthreads();

    const int ktn = (q0 + 128) >> 6;
    for (int kt = 0; kt < ktn; kt++) {
        const int k0 = kt * 64;
#pragma unroll
        for (int i = 0; i < 8; i++) {
            int idx = tid + i * 256;
            int r = idx >> 5;
            int d = (idx & 31) << 2;
            float4 kv = *(const float4*)&Kg[(size_t)(k0 + r) * HD_ + d];
            float4 vv = *(const float4*)&Vg[(size_t)(k0 + r) * HD_ + d];
            float kf[4] = {kv.x, kv.y, kv.z, kv.w};
            float vf[4] = {vv.x, vv.y, vv.z, vv.w};
            float khf[4], klf[4], vhf[4], vlf[4];
#pragma unroll
            for (int e = 0; e < 4; e++) {
                khf[e] = __bfloat162float(__float2bfloat16(kf[e]));
                klf[e] = kf[e] - khf[e];
                vhf[e] = __bfloat162float(__float2bfloat16(vf[e]));
                vlf[e] = vf[e] - vhf[e];
            }
            uint32_t* pkh = (uint32_t*)&sKh[r * STQ + d];
            uint32_t* pkl = (uint32_t*)&sKl[r * STQ + d];
            uint32_t* pvh = (uint32_t*)&sVh[r * STQ + d];
            uint32_t* pvl = (uint32_t*)&sVl[r * STQ + d];
            pkh[0] = packbf(khf[0], khf[1]); pkh[1] = packbf(khf[2], khf[3]);
            pkl[0] = packbf(klf[0], klf[1]); pkl[1] = packbf(klf[2], klf[3]);
            pvh[0] = packbf(vhf[0], vhf[1]); pvh[1] = packbf(vhf[2], vhf[3]);
            pvl[0] = packbf(vlf[0], vlf[1]); pvl[1] = packbf(vlf[2], vlf[3]);
        }
        __syncthreads();

        const bool active = (k0 <= q0 + w * 16 + 15);
        if (active) {
            float S[8][4];
#pragma unroll
            for (int t = 0; t < 8; t++)
#pragma unroll
                for (int r = 0; r < 4; r++) S[t][r] = 0.f;

#pragma unroll
            for (int kc = 0; kc < 8; kc++) {
                const int col = kc * 16 + fcol;
                uint32_t qh[4], ql[4];
                uint32_t qoff = ((w * 16 + frow) * STQ + col) * 2;
                LDSM_X4(qh, uQh + qoff);
                LDSM_X4(ql, uQl + qoff);
#pragma unroll
                for (int p = 0; p < 4; p++) {
                    uint32_t koff = ((p * 16 + frow) * STQ + col) * 2;
                    uint32_t kh[4], kl[4];
                    LDSM_X4(kh, uKh + koff);
                    LDSM_X4(kl, uKl + koff);
                    uint32_t bh0[2] = {kh[0], kh[2]};
                    uint32_t bh1[2] = {kh[1], kh[3]};
                    uint32_t bl0[2] = {kl[0], kl[2]};
                    uint32_t bl1[2] = {kl[1], kl[3]};
                    // alternate accumulators between passes
                    MMA_BF16(S[2 * p], qh, bh0);
                    MMA_BF16(S[2 * p + 1], qh, bh1);
                    MMA_BF16(S[2 * p], ql, bh0);
                    MMA_BF16(S[2 * p + 1], ql, bh1);
                    MMA_BF16(S[2 * p], qh, bl0);
                    MMA_BF16(S[2 * p + 1], qh, bl1);
                }
            }

            const bool maskneed = (k0 + 63 > row0);
#pragma unroll
            for (int t = 0; t < 8; t++) {
                int c0 = k0 + 8 * t + 2 * qp;
#pragma unroll
                for (int r = 0; r < 4; r++) {
                    S[t][r] *= sc;
                    if (maskneed) {
                        int colg = c0 + (r & 1);
                        int rowg = (r < 2) ? row0 : row1;
                        if (colg > rowg) S[t][r] = -1e9f;
                    }
                }
            }

            float rm0 = -1e30f, rm1 = -1e30f;
#pragma unroll
            for (int t = 0; t < 8; t++) {
                rm0 = fmaxf(rm0, fmaxf(S[t][0], S[t][1]));
                rm1 = fmaxf(rm1, fmaxf(S[t][2], S[t][3]));
            }
            rm0 = fmaxf(rm0, __shfl_xor_sync(0xffffffffu, rm0, 1));
            rm0 = fmaxf(rm0, __shfl_xor_sync(0xffffffffu, rm0, 2));
            rm1 = fmaxf(rm1, __shfl_xor_sync(0xffffffffu, rm1, 1));
            rm1 = fmaxf(rm1, __shfl_xor_sync(0xffffffffu, rm1, 2));
            float mn0 = fmaxf(m0, rm0), mn1 = fmaxf(m1, rm1);
            float a0 = __expf(m0 - mn0), a1 = __expf(m1 - mn1);
            float rs0 = 0.f, rs1 = 0.f;
#pragma unroll
            for (int t = 0; t < 8; t++) {
                S[t][0] = __expf(S[t][0] - mn0);
                S[t][1] = __expf(S[t][1] - mn0);
                S[t][2] = __expf(S[t][2] - mn1);
                S[t][3] = __expf(S[t][3] - mn1);
                rs0 += S[t][0] + S[t][1];
                rs1 += S[t][2] + S[t][3];
            }
            rs0 += __shfl_xor_sync(0xffffffffu, rs0, 1);
            rs0 += __shfl_xor_sync(0xffffffffu, rs0, 2);
            rs1 += __shfl_xor_sync(0xffffffffu, rs1, 1);
            rs1 += __shfl_xor_sync(0xffffffffu, rs1, 2);
            l0 = l0 * a0 + rs0;
            l1 = l1 * a1 + rs1;
            m0 = mn0;
            m1 = mn1;
#pragma unroll
            for (int t = 0; t < 16; t++) {
                O[t][0] *= a0; O[t][1] *= a0;
                O[t][2] *= a1; O[t][3] *= a1;
            }

            uint32_t ph[4][4], pl[4][4];
#pragma unroll
            for (int kc2 = 0; kc2 < 4; kc2++) {
                int t0 = 2 * kc2, t1 = 2 * kc2 + 1;
                float src[8] = {S[t0][0], S[t0][1], S[t0][2], S[t0][3],
                                S[t1][0], S[t1][1], S[t1][2], S[t1][3]};
                float hv[8], lv[8];
#pragma unroll
                for (int e = 0; e < 8; e++) {
                    hv[e] = __bfloat162float(__float2bfloat16(src[e]));
                    lv[e] = src[e] - hv[e];
                }
                ph[kc2][0] = packbf(hv[0], hv[1]);
                ph[kc2][1] = packbf(hv[2], hv[3]);
                ph[kc2][2] = packbf(hv[4], hv[5]);
                ph[kc2][3] = packbf(hv[6], hv[7]);
                pl[kc2][0] = packbf(lv[0], lv[1]);
                pl[kc2][1] = packbf(lv[2], lv[3]);
                pl[kc2][2] = packbf(lv[4], lv[5]);
                pl[kc2][3] = packbf(lv[6], lv[7]);
            }

#pragma unroll
            for (int kc2 = 0; kc2 < 4; kc2++) {
#pragma unroll
                for (int p = 0; p < 8; p++) {
                    uint32_t voff = ((kc2 * 16 + frow) * STQ + p * 16 + fcol) * 2;
                    uint32_t vh[4], vl[4];
                    LDSM_X4T(vh, uVh + voff);
                    LDSM_X4T(vl, uVl + voff);
                    uint32_t bh0[2] = {vh[0], vh[1]};
                    uint32_t bh1[2] = {vh[2], vh[3]};
                    uint32_t bl0[2] = {vl[0], vl[1]};
                    uint32_t bl1[2] = {vl[2], vl[3]};
                    // alternate accumulators between passes
                    MMA_BF16(O[2 * p], ph[kc2], bh0);
                    MMA_BF16(O[2 * p + 1], ph[kc2], bh1);
                    MMA_BF16(O[2 * p], pl[kc2], bh0);
                    MMA_BF16(O[2 * p + 1], pl[kc2], bh1);
                    MMA_BF16(O[2 * p], ph[kc2], bl0);
                    MMA_BF16(O[2 * p + 1], ph[kc2], bl1);
                }
            }
        }
        __syncthreads();
    }

    float inv0 = 1.f / l0, inv1 = 1.f / l1;
    size_t base0 = (((size_t)b * S_ + row0) * NH_ + h) * HD_;
    size_t base1 = (((size_t)b * S_ + row1) * NH_ + h) * HD_;
#pragma unroll
    for (int t = 0; t < 16; t++) {
        int d = 8 * t + 2 * qp;
        *(float2*)&g_ctx[base0 + d] = make_float2(O[t][0] * inv0, O[t][1] * inv0);
        *(float2*)&g_ctx[base1 + d] = make_float2(O[t][2] * inv1, O[t][3] * inv1);
    }
}

// ---------------------------------------------------------------------------
extern "C" void kernel_launch(void* const* d_in, const int* in_sizes, int n_in,
                              void* d_out, int out_size) {
    (void)in_sizes; (void)n_in; (void)out_size;
    const float* x     = (const float*)d_in[0];
    const float* w_qkv = (const float*)d_in[1];
    const float* w_o   = (const float*)d_in[2];
    const float* cosT  = (const float*)d_in[3];
    const float* sinT  = (const float*)d_in[4];
    float* out = (float*)d_out;

    cudaFuncSetAttribute(attn_mma_kernel, cudaFuncAttributeMaxDynamicSharedMemorySize, ATTN_SMEM);

    // 1) QKV projection: M=4096, N=6144
    gemm_bf16_kernel<0><<<dim3(6144 / 128, 4096 / 128), 256>>>(x, w_qkv, nullptr);

    // 2) RoPE on Q and K
    rope_kernel<<<(2 * B_ * NH_ * S_ * 64) / 256, 256>>>(cosT, sinT);

    // 3) Flash attention
    attn_mma_kernel<<<dim3(S_ / 128, B_ * NH_), 256, ATTN_SMEM>>>();

    // 4) Output projection: M=4096, N=2048
    gemm_bf16_kernel<1><<<dim3(2048 / 128, 4096 / 128), 256>>>(nullptr, w_o, out);
}

// round 10
// speedup vs baseline: 1.3610x; 1.2849x over previous
#include <cuda_runtime.h>
#include <cuda_fp16.h>
#include <cstdint>
#include <math.h>

#define B_   2
#define S_   2048
#define HID_ 2048
#define NH_  16
#define HD_  128
#define KDIM 2048

__device__ float g_qkv[(size_t)3 * B_ * NH_ * S_ * HD_];   // [which][b][h][s][d]
__device__ float g_ctx[(size_t)B_ * S_ * HID_];            // [b][s][h][d] row-major [M][2048]

// ---------------- helpers ----------------
__device__ __forceinline__ uint32_t s2u(const void* p) {
    return (uint32_t)__cvta_generic_to_shared(p);
}
// pack (lo, hi) floats -> f16x2 (lo in low half)
__device__ __forceinline__ uint32_t packh(float lo, float hi) {
    uint32_t r;
    asm("cvt.rn.f16x2.f32 %0, %1, %2;" : "=r"(r) : "f"(hi), "f"(lo));
    return r;
}

#define MMA_F16(d, a, b)                                                      \
    asm volatile(                                                             \
        "mma.sync.aligned.m16n8k16.row.col.f32.f16.f16.f32 "                  \
        "{%0,%1,%2,%3}, {%4,%5,%6,%7}, {%8,%9}, {%0,%1,%2,%3};\n"             \
        : "+f"((d)[0]), "+f"((d)[1]), "+f"((d)[2]), "+f"((d)[3])              \
        : "r"((a)[0]), "r"((a)[1]), "r"((a)[2]), "r"((a)[3]),                 \
          "r"((b)[0]), "r"((b)[1]))

#define LDSM_X4(r, addr)                                                      \
    asm volatile("ldmatrix.sync.aligned.m8n8.x4.shared.b16 {%0,%1,%2,%3}, [%4];" \
                 : "=r"((r)[0]), "=r"((r)[1]), "=r"((r)[2]), "=r"((r)[3])     \
                 : "r"(addr))

#define LDSM_X4T(r, addr)                                                     \
    asm volatile("ldmatrix.sync.aligned.m8n8.x4.trans.shared.b16 {%0,%1,%2,%3}, [%4];" \
                 : "=r"((r)[0]), "=r"((r)[1]), "=r"((r)[2]), "=r"((r)[3])     \
                 : "r"(addr))

// ---------------------------------------------------------------------------
// 2-pass fp16 tensor-core GEMM: C[m][n] = sum_k A[m][k]*W[n][k]
// A split into fp16 hi+lo; W rounded to fp16.  D = Ah*Bf + Al*Bf.
// BM=BN=128, BK=32, 256 thr, 8 warps (4 warpM x 2 warpN), warp tile 32x64.
// MODE 0: A = x, scatter q/k/v into g_qkv.  MODE 1: A = g_ctx, write Cout.
// ---------------------------------------------------------------------------
#define SMSTRIDE 40

template <int MODE>
__global__ __launch_bounds__(256, 2)
void gemm_f16_kernel(const float* __restrict__ Ain,
                     const float* __restrict__ W,
                     float* __restrict__ Cout) {
    const int m0 = blockIdx.y * 128;
    const int n0 = blockIdx.x * 128;
    const int tid = threadIdx.x;
    const int lane = tid & 31;
    const int warp = tid >> 5;
    const int warpM = warp & 3;
    const int warpN = warp >> 2;

    const float* A = (MODE == 0) ? Ain : g_ctx;

    __shared__ __half Ah[128 * SMSTRIDE];
    __shared__ __half Al[128 * SMSTRIDE];
    __shared__ __half Bf[128 * SMSTRIDE];

    float C[2][8][4];
#pragma unroll
    for (int mt = 0; mt < 2; mt++)
#pragma unroll
        for (int nt = 0; nt < 8; nt++)
#pragma unroll
            for (int r = 0; r < 4; r++) C[mt][nt][r] = 0.f;

    const uint32_t uAh = s2u(Ah), uAl = s2u(Al), uBf = s2u(Bf);
    const int g = lane >> 2;
    const int qp = lane & 3;
    const int frow = lane & 15;
    const int fcol = (lane >> 4) << 3;

    for (int k0 = 0; k0 < KDIM; k0 += 32) {
        // ---- load fp32 tiles, split A hi/lo, round B ----
#pragma unroll
        for (int t = 0; t < 4; t++) {
            int l = tid + t * 256;
            int row = l >> 3;
            int kc = (l & 7) * 4;
            float4 av = *(const float4*)&A[(size_t)(m0 + row) * KDIM + k0 + kc];
            float4 bv = *(const float4*)&W[(size_t)(n0 + row) * KDIM + k0 + kc];
            float af[4] = {av.x, av.y, av.z, av.w};
            float ahf[4], alf[4];
#pragma unroll
            for (int e = 0; e < 4; e++) {
                ahf[e] = __half2float(__float2half_rn(af[e]));
                alf[e] = af[e] - ahf[e];
            }
            uint32_t* pAh = (uint32_t*)&Ah[row * SMSTRIDE + kc];
            uint32_t* pAl = (uint32_t*)&Al[row * SMSTRIDE + kc];
            uint32_t* pBf = (uint32_t*)&Bf[row * SMSTRIDE + kc];
            pAh[0] = packh(ahf[0], ahf[1]); pAh[1] = packh(ahf[2], ahf[3]);
            pAl[0] = packh(alf[0], alf[1]); pAl[1] = packh(alf[2], alf[3]);
            pBf[0] = packh(bv.x, bv.y);     pBf[1] = packh(bv.z, bv.w);
        }
        __syncthreads();

#pragma unroll
        for (int kc = 0; kc < 2; kc++) {
            const int col = kc * 16 + fcol;
            uint32_t a_hi[2][4], a_lo[2][4];
#pragma unroll
            for (int mt = 0; mt < 2; mt++) {
                uint32_t off = ((warpM * 32 + mt * 16 + frow) * SMSTRIDE + col) * 2;
                LDSM_X4(a_hi[mt], uAh + off);
                LDSM_X4(a_lo[mt], uAl + off);
            }
#pragma unroll
            for (int p = 0; p < 4; p++) {
                uint32_t off = ((warpN * 64 + p * 16 + frow) * SMSTRIDE + col) * 2;
                uint32_t kb[4];
                LDSM_X4(kb, uBf + off);
                uint32_t b0[2] = {kb[0], kb[2]};
                uint32_t b1[2] = {kb[1], kb[3]};
#pragma unroll
                for (int mt = 0; mt < 2; mt++) {
                    MMA_F16(C[mt][2 * p], a_hi[mt], b0);
                    MMA_F16(C[mt][2 * p + 1], a_hi[mt], b1);
                    MMA_F16(C[mt][2 * p], a_lo[mt], b0);
                    MMA_F16(C[mt][2 * p + 1], a_lo[mt], b1);
                }
            }
        }
        __syncthreads();
    }

    // ---- epilogue ----
#pragma unroll
    for (int mt = 0; mt < 2; mt++) {
#pragma unroll
        for (int nt = 0; nt < 8; nt++) {
            int gm0 = m0 + warpM * 32 + mt * 16 + g;
            int gn = n0 + warpN * 64 + nt * 8 + qp * 2;
            float2 v0 = make_float2(C[mt][nt][0], C[mt][nt][1]);
            float2 v1 = make_float2(C[mt][nt][2], C[mt][nt][3]);
            if (MODE == 0) {
                int which = gn >> 11;
                int rem = gn & 2047;
                int h = rem >> 7;
                int d = rem & 127;
#pragma unroll
                for (int rr = 0; rr < 2; rr++) {
                    int gm = gm0 + rr * 8;
                    int b = gm >> 11;
                    int s = gm & 2047;
                    size_t off = (size_t)which * ((size_t)B_ * NH_ * S_ * HD_) +
                                 (((size_t)(b * NH_ + h)) * S_ + s) * HD_ + d;
                    *(float2*)&g_qkv[off] = rr ? v1 : v0;
                }
            } else {
                *(float2*)&Cout[(size_t)gm0 * HID_ + gn] = v0;
                *(float2*)&Cout[(size_t)(gm0 + 8) * HID_ + gn] = v1;
            }
        }
    }
}

// ---------------------------------------------------------------------------
// RoPE in-place on Q and K halves of g_qkv.
// ---------------------------------------------------------------------------
__global__ __launch_bounds__(256)
void rope_kernel(const float* __restrict__ cosT, const float* __restrict__ sinT) {
    long long t = (long long)blockIdx.x * 256 + threadIdx.x;
    int d = (int)(t & 63);
    long long row = t >> 6;
    int s = (int)(row % S_);
    float* p = g_qkv + row * HD_;
    float x1 = p[d];
    float x2 = p[d + 64];
    float c1 = cosT[s * HD_ + d];
    float s1 = sinT[s * HD_ + d];
    float c2 = cosT[s * HD_ + d + 64];
    float s2 = sinT[s * HD_ + d + 64];
    p[d]      = x1 * c1 - x2 * s1;
    p[d + 64] = x2 * c2 + x1 * s2;
}

// ---------------------------------------------------------------------------
// 2-pass fp16 tensor-core causal flash attention. BQ=128, BK=64, 256 threads.
// Q split hi/lo fp16, K rounded fp16; P split hi/lo, V rounded fp16.
// ---------------------------------------------------------------------------
#define STQ 136
#define ATTN_SMEM ((2 * 128 + 2 * 64) * STQ * 2)   // 104448 bytes

__global__ __launch_bounds__(256, 1)
void attn_mma_kernel() {
    extern __shared__ char smraw[];
    __half* sQh = (__half*)smraw;
    __half* sQl = sQh + 128 * STQ;
    __half* sKf = sQl + 128 * STQ;
    __half* sVf = sKf + 64 * STQ;

    const int tid = threadIdx.x;
    const int lane = tid & 31;
    const int w = tid >> 5;
    const int qp = lane & 3;
    const int g = lane >> 2;
    const int frow = lane & 15;
    const int fcol = (lane >> 4) << 3;

    const int qt = blockIdx.x;
    const int bh = blockIdx.y;
    const int b = bh >> 4;
    const int h = bh & 15;
    const int q0 = qt * 128;

    const size_t hs = (size_t)S_ * HD_;
    const float* Qg = g_qkv + (size_t)bh * hs;
    const float* Kg = g_qkv + (size_t)(B_ * NH_ + bh) * hs;
    const float* Vg = g_qkv + (size_t)(2 * B_ * NH_ + bh) * hs;

    // ---- load Q tile (128 x 128), split to hi/lo fp16 ----
#pragma unroll
    for (int i = 0; i < 16; i++) {
        int idx = tid + i * 256;
        int r = idx >> 5;
        int d = (idx & 31) << 2;
        float4 v = *(const float4*)&Qg[(size_t)(q0 + r) * HD_ + d];
        float f[4] = {v.x, v.y, v.z, v.w};
        float hf[4], lf[4];
#pragma unroll
        for (int e = 0; e < 4; e++) {
            hf[e] = __half2float(__float2half_rn(f[e]));
            lf[e] = f[e] - hf[e];
        }
        uint32_t* ph = (uint32_t*)&sQh[r * STQ + d];
        uint32_t* pl = (uint32_t*)&sQl[r * STQ + d];
        ph[0] = packh(hf[0], hf[1]); ph[1] = packh(hf[2], hf[3]);
        pl[0] = packh(lf[0], lf[1]); pl[1] = packh(lf[2], lf[3]);
    }

    const uint32_t uQh = s2u(sQh), uQl = s2u(sQl);
    const uint32_t uKf = s2u(sKf), uVf = s2u(sVf);

    float O[16][4];
#pragma unroll
    for (int t = 0; t < 16; t++)
#pragma unroll
        for (int r = 0; r < 4; r++) O[t][r] = 0.f;
    float m0 = -1e30f, m1 = -1e30f, l0 = 0.f, l1 = 0.f;

    const float sc = 0.08838834764831845f;
    const int row0 = q0 + w * 16 + g;
    const int row1 = row0 + 8;

    __syncthreads();

    const int ktn = (q0 + 128) >> 6;
    for (int kt = 0; kt < ktn; kt++) {
        const int k0 = kt * 64;
        // ---- load K,V tiles (64 x 128 each), round to fp16 ----
#pragma unroll
        for (int i = 0; i < 8; i++) {
            int idx = tid + i * 256;
            int r = idx >> 5;
            int d = (idx & 31) << 2;
            float4 kv = *(const float4*)&Kg[(size_t)(k0 + r) * HD_ + d];
            float4 vv = *(const float4*)&Vg[(size_t)(k0 + r) * HD_ + d];
            uint32_t* pk = (uint32_t*)&sKf[r * STQ + d];
            uint32_t* pv = (uint32_t*)&sVf[r * STQ + d];
            pk[0] = packh(kv.x, kv.y); pk[1] = packh(kv.z, kv.w);
            pv[0] = packh(vv.x, vv.y); pv[1] = packh(vv.z, vv.w);
        }
        __syncthreads();

        const bool active = (k0 <= q0 + w * 16 + 15);
        if (active) {
            // ---- S = Q K^T ----
            float S[8][4];
#pragma unroll
            for (int t = 0; t < 8; t++)
#pragma unroll
                for (int r = 0; r < 4; r++) S[t][r] = 0.f;

#pragma unroll
            for (int kc = 0; kc < 8; kc++) {
                const int col = kc * 16 + fcol;
                uint32_t qh[4], ql[4];
                uint32_t qoff = ((w * 16 + frow) * STQ + col) * 2;
                LDSM_X4(qh, uQh + qoff);
                LDSM_X4(ql, uQl + qoff);
#pragma unroll
                for (int p = 0; p < 4; p++) {
                    uint32_t koff = ((p * 16 + frow) * STQ + col) * 2;
                    uint32_t kf[4];
                    LDSM_X4(kf, uKf + koff);
                    uint32_t b0[2] = {kf[0], kf[2]};
                    uint32_t b1[2] = {kf[1], kf[3]};
                    MMA_F16(S[2 * p], qh, b0);
                    MMA_F16(S[2 * p + 1], qh, b1);
                    MMA_F16(S[2 * p], ql, b0);
                    MMA_F16(S[2 * p + 1], ql, b1);
                }
            }

            // ---- scale + causal mask ----
            const bool maskneed = (k0 + 63 > row0);
#pragma unroll
            for (int t = 0; t < 8; t++) {
                int c0 = k0 + 8 * t + 2 * qp;
#pragma unroll
                for (int r = 0; r < 4; r++) {
                    S[t][r] *= sc;
                    if (maskneed) {
                        int colg = c0 + (r & 1);
                        int rowg = (r < 2) ? row0 : row1;
                        if (colg > rowg) S[t][r] = -1e9f;
                    }
                }
            }

            // ---- online softmax ----
            float rm0 = -1e30f, rm1 = -1e30f;
#pragma unroll
            for (int t = 0; t < 8; t++) {
                rm0 = fmaxf(rm0, fmaxf(S[t][0], S[t][1]));
                rm1 = fmaxf(rm1, fmaxf(S[t][2], S[t][3]));
            }
            rm0 = fmaxf(rm0, __shfl_xor_sync(0xffffffffu, rm0, 1));
            rm0 = fmaxf(rm0, __shfl_xor_sync(0xffffffffu, rm0, 2));
            rm1 = fmaxf(rm1, __shfl_xor_sync(0xffffffffu, rm1, 1));
            rm1 = fmaxf(rm1, __shfl_xor_sync(0xffffffffu, rm1, 2));
            float mn0 = fmaxf(m0, rm0), mn1 = fmaxf(m1, rm1);
            float a0 = __expf(m0 - mn0), a1 = __expf(m1 - mn1);
            float rs0 = 0.f, rs1 = 0.f;
#pragma unroll
            for (int t = 0; t < 8; t++) {
                S[t][0] = __expf(S[t][0] - mn0);
                S[t][1] = __expf(S[t][1] - mn0);
                S[t][2] = __expf(S[t][2] - mn1);
                S[t][3] = __expf(S[t][3] - mn1);
                rs0 += S[t][0] + S[t][1];
                rs1 += S[t][2] + S[t][3];
            }
            rs0 += __shfl_xor_sync(0xffffffffu, rs0, 1);
            rs0 += __shfl_xor_sync(0xffffffffu, rs0, 2);
            rs1 += __shfl_xor_sync(0xffffffffu, rs1, 1);
            rs1 += __shfl_xor_sync(0xffffffffu, rs1, 2);
            l0 = l0 * a0 + rs0;
            l1 = l1 * a1 + rs1;
            m0 = mn0;
            m1 = mn1;
#pragma unroll
            for (int t = 0; t < 16; t++) {
                O[t][0] *= a0; O[t][1] *= a0;
                O[t][2] *= a1; O[t][3] *= a1;
            }

            // ---- P fragments (hi/lo fp16) in-register ----
            uint32_t ph[4][4], pl[4][4];
#pragma unroll
            for (int kc2 = 0; kc2 < 4; kc2++) {
                int t0 = 2 * kc2, t1 = 2 * kc2 + 1;
                float src[8] = {S[t0][0], S[t0][1], S[t0][2], S[t0][3],
                                S[t1][0], S[t1][1], S[t1][2], S[t1][3]};
                float hv[8], lv[8];
#pragma unroll
                for (int e = 0; e < 8; e++) {
                    hv[e] = __half2float(__float2half_rn(src[e]));
                    lv[e] = src[e] - hv[e];
                }
                ph[kc2][0] = packh(hv[0], hv[1]);
                ph[kc2][1] = packh(hv[2], hv[3]);
                ph[kc2][2] = packh(hv[4], hv[5]);
                ph[kc2][3] = packh(hv[6], hv[7]);
                pl[kc2][0] = packh(lv[0], lv[1]);
                pl[kc2][1] = packh(lv[2], lv[3]);
                pl[kc2][2] = packh(lv[4], lv[5]);
                pl[kc2][3] = packh(lv[6], lv[7]);
            }

            // ---- O += P V  (V via ldmatrix.trans, single fp16) ----
#pragma unroll
            for (int kc2 = 0; kc2 < 4; kc2++) {
#pragma unroll
                for (int p = 0; p < 8; p++) {
                    uint32_t voff = ((kc2 * 16 + frow) * STQ + p * 16 + fcol) * 2;
                    uint32_t vf[4];
                    LDSM_X4T(vf, uVf + voff);
                    uint32_t b0[2] = {vf[0], vf[1]};
                    uint32_t b1[2] = {vf[2], vf[3]};
                    MMA_F16(O[2 * p], ph[kc2], b0);
                    MMA_F16(O[2 * p + 1], ph[kc2], b1);
                    MMA_F16(O[2 * p], pl[kc2], b0);
                    MMA_F16(O[2 * p + 1], pl[kc2], b1);
                }
            }
        }
        __syncthreads();
    }

    // ---- normalize + write ctx [b][s][h][d] ----
    float inv0 = 1.f / l0, inv1 = 1.f / l1;
    size_t base0 = (((size_t)b * S_ + row0) * NH_ + h) * HD_;
    size_t base1 = (((size_t)b * S_ + row1) * NH_ + h) * HD_;
#pragma unroll
    for (int t = 0; t < 16; t++) {
        int d = 8 * t + 2 * qp;
        *(float2*)&g_ctx[base0 + d] = make_float2(O[t][0] * inv0, O[t][1] * inv0);
        *(float2*)&g_ctx[base1 + d] = make_float2(O[t][2] * inv1, O[t][3] * inv1);
    }
}

// ---------------------------------------------------------------------------
extern "C" void kernel_launch(void* const* d_in, const int* in_sizes, int n_in,
                              void* d_out, int out_size) {
    (void)in_sizes; (void)n_in; (void)out_size;
    const float* x     = (const float*)d_in[0];
    const float* w_qkv = (const float*)d_in[1];
    const float* w_o   = (const float*)d_in[2];
    const float* cosT  = (const float*)d_in[3];
    const float* sinT  = (const float*)d_in[4];
    float* out = (float*)d_out;

    cudaFuncSetAttribute(attn_mma_kernel, cudaFuncAttributeMaxDynamicSharedMemorySize, ATTN_SMEM);

    // 1) QKV projection: M=4096, N=6144
    gemm_f16_kernel<0><<<dim3(6144 / 128, 4096 / 128), 256>>>(x, w_qkv, nullptr);

    // 2) RoPE on Q and K
    rope_kernel<<<(2 * B_ * NH_ * S_ * 64) / 256, 256>>>(cosT, sinT);

    // 3) Flash attention
    attn_mma_kernel<<<dim3(S_ / 128, B_ * NH_), 256, ATTN_SMEM>>>();

    // 4) Output projection: M=4096, N=2048
    gemm_f16_kernel<1><<<dim3(2048 / 128, 4096 / 128), 256>>>(nullptr, w_o, out);
}

// round 12
// speedup vs baseline: 1.5363x; 1.1288x over previous
#include <cuda_runtime.h>
#include <cuda_fp16.h>
#include <cstdint>
#include <math.h>

#define B_   2
#define S_   2048
#define HID_ 2048
#define NH_  16
#define HD_  128
#define KDIM 2048
#define BNHS (B_ * NH_ * S_)

typedef __half h16;

// ---- persistent buffers ----
__device__ float g_qkv[(size_t)3 * BNHS * HD_];   // [which][b][h][s][d] fp32
__device__ h16 g_xh[(size_t)B_ * S_ * HID_];
__device__ h16 g_xl[(size_t)B_ * S_ * HID_];
__device__ h16 g_wqf[(size_t)3 * HID_ * HID_];
__device__ h16 g_wof[(size_t)HID_ * HID_];
__device__ h16 g_qh[(size_t)BNHS * HD_];
__device__ h16 g_ql[(size_t)BNHS * HD_];
__device__ h16 g_kf[(size_t)BNHS * HD_];
__device__ h16 g_vf[(size_t)BNHS * HD_];
__device__ h16 g_ctxh[(size_t)B_ * S_ * HID_];    // [b][s][h][d]
__device__ h16 g_ctxl[(size_t)B_ * S_ * HID_];

// ---------------- helpers ----------------
__device__ __forceinline__ uint32_t s2u(const void* p) {
    return (uint32_t)__cvta_generic_to_shared(p);
}
__device__ __forceinline__ uint32_t packh(float lo, float hi) {
    uint32_t r;
    asm("cvt.rn.f16x2.f32 %0, %1, %2;" : "=r"(r) : "f"(hi), "f"(lo));
    return r;
}

#define MMA_F16(d, a, b)                                                      \
    asm volatile(                                                             \
        "mma.sync.aligned.m16n8k16.row.col.f32.f16.f16.f32 "                  \
        "{%0,%1,%2,%3}, {%4,%5,%6,%7}, {%8,%9}, {%0,%1,%2,%3};\n"             \
        : "+f"((d)[0]), "+f"((d)[1]), "+f"((d)[2]), "+f"((d)[3])              \
        : "r"((a)[0]), "r"((a)[1]), "r"((a)[2]), "r"((a)[3]),                 \
          "r"((b)[0]), "r"((b)[1]))

#define LDSM_X4(r, addr)                                                      \
    asm volatile("ldmatrix.sync.aligned.m8n8.x4.shared.b16 {%0,%1,%2,%3}, [%4];" \
                 : "=r"((r)[0]), "=r"((r)[1]), "=r"((r)[2]), "=r"((r)[3])     \
                 : "r"(addr))

#define LDSM_X4T(r, addr)                                                     \
    asm volatile("ldmatrix.sync.aligned.m8n8.x4.trans.shared.b16 {%0,%1,%2,%3}, [%4];" \
                 : "=r"((r)[0]), "=r"((r)[1]), "=r"((r)[2]), "=r"((r)[3])     \
                 : "r"(addr))

#define CP_ASYNC16(dst, src)                                                  \
    asm volatile("cp.async.cg.shared.global [%0], [%1], 16;" ::               \
                 "r"(dst), "l"(src))
#define CP_COMMIT() asm volatile("cp.async.commit_group;" ::: "memory")
#define CP_WAIT1()  asm volatile("cp.async.wait_group 1;" ::: "memory")
#define CP_WAIT0()  asm volatile("cp.async.wait_group 0;" ::: "memory")

// ---------------------------------------------------------------------------
// Prep: split fp32 -> fp16 hi/lo, and plain fp32 -> fp16 convert.
// ---------------------------------------------------------------------------
__global__ __launch_bounds__(256)
void split_kernel(const float* __restrict__ src, h16* __restrict__ h,
                  h16* __restrict__ l, int n4) {
    int i = blockIdx.x * 256 + threadIdx.x;
    if (i >= n4) return;
    float4 v = *(const float4*)&src[(size_t)i * 4];
    float f[4] = {v.x, v.y, v.z, v.w};
    float hf[4], lf[4];
#pragma unroll
    for (int e = 0; e < 4; e++) {
        hf[e] = __half2float(__float2half_rn(f[e]));
        lf[e] = f[e] - hf[e];
    }
    *(uint2*)&h[(size_t)i * 4] = make_uint2(packh(hf[0], hf[1]), packh(hf[2], hf[3]));
    *(uint2*)&l[(size_t)i * 4] = make_uint2(packh(lf[0], lf[1]), packh(lf[2], lf[3]));
}

__global__ __launch_bounds__(256)
void conv_kernel(const float* __restrict__ src, h16* __restrict__ dst, int n4) {
    int i = blockIdx.x * 256 + threadIdx.x;
    if (i >= n4) return;
    float4 v = *(const float4*)&src[(size_t)i * 4];
    *(uint2*)&dst[(size_t)i * 4] = make_uint2(packh(v.x, v.y), packh(v.z, v.w));
}

// ---------------------------------------------------------------------------
// Pre-split 2-pass fp16 GEMM: C[m][n] = sum_k A[m][k]*W[n][k]
// A = Ah + Al (fp16), W single fp16. BM=BN=128, BK=32/stage, 2-stage cp.async.
// 256 thr, 8 warps (4 warpM x 2 warpN), warp tile 32x64.
// MODE 0: scatter fp32 q/k/v into g_qkv.  MODE 1: fp32 out.
// ---------------------------------------------------------------------------
#define GST 40                        // halfs per row (32 + 8 pad)
#define ARRB (128 * GST * 2)          // bytes per array = 10240
#define STGB (3 * ARRB)               // bytes per stage = 30720
#define GSMEM (2 * STGB)              // 61440

template <int MODE>
__global__ __launch_bounds__(256, 2)
void gemm_f16_kernel(const h16* __restrict__ Agh, const h16* __restrict__ Agl,
                     const h16* __restrict__ Bgf, float* __restrict__ Cout) {
    extern __shared__ char smem[];
    const uint32_t sbase = s2u(smem);
    const int m0 = blockIdx.y * 128;
    const int n0 = blockIdx.x * 128;
    const int tid = threadIdx.x;
    const int lane = tid & 31;
    const int warp = tid >> 5;
    const int warpM = warp & 3;
    const int warpN = warp >> 2;

    const int g = lane >> 2;
    const int qp = lane & 3;
    const int frow = lane & 15;
    const int fcol = (lane >> 4) << 3;

    float C[2][8][4];
#pragma unroll
    for (int mt = 0; mt < 2; mt++)
#pragma unroll
        for (int nt = 0; nt < 8; nt++)
#pragma unroll
            for (int r = 0; r < 4; r++) C[mt][nt][r] = 0.f;

    // load slots: per array, 512 x 16B chunks; each thread does 2.
    // idx = tid + t*256 (0..511): row = idx>>2, quarter = idx&3 (8 halfs).
#define ISSUE(s)                                                              \
    do {                                                                      \
        const int k0_ = (s) * 32;                                             \
        const uint32_t sb_ = sbase + ((s) & 1) * STGB;                        \
        _Pragma("unroll")                                                     \
        for (int t = 0; t < 2; t++) {                                         \
            int idx = tid + t * 256;                                          \
            int row = idx >> 2;                                               \
            int qtr = (idx & 3) * 8;                                          \
            uint32_t soff = (row * GST + qtr) * 2;                            \
            size_t ga = (size_t)(m0 + row) * KDIM + k0_ + qtr;                \
            size_t gb = (size_t)(n0 + row) * KDIM + k0_ + qtr;                \
            CP_ASYNC16(sb_ + soff,            Agh + ga);                      \
            CP_ASYNC16(sb_ + ARRB + soff,     Agl + ga);                      \
            CP_ASYNC16(sb_ + 2 * ARRB + soff, Bgf + gb);                      \
        }                                                                     \
        CP_COMMIT();                                                          \
    } while (0)

    ISSUE(0);
    ISSUE(1);

    const int NST = KDIM / 32;   // 64
#pragma unroll 1
    for (int s = 0; s < NST; s++) {
        if (s == NST - 1) CP_WAIT0(); else CP_WAIT1();
        __syncthreads();

        const uint32_t uAh = sbase + (s & 1) * STGB;
        const uint32_t uAl = uAh + ARRB;
        const uint32_t uBf = uAh + 2 * ARRB;

#pragma unroll
        for (int kc = 0; kc < 2; kc++) {
            const int col = kc * 16 + fcol;
            uint32_t a_hi[2][4], a_lo[2][4];
#pragma unroll
            for (int mt = 0; mt < 2; mt++) {
                uint32_t off = ((warpM * 32 + mt * 16 + frow) * GST + col) * 2;
                LDSM_X4(a_hi[mt], uAh + off);
                LDSM_X4(a_lo[mt], uAl + off);
            }
#pragma unroll
            for (int p = 0; p < 4; p++) {
                uint32_t off = ((warpN * 64 + p * 16 + frow) * GST + col) * 2;
                uint32_t kb[4];
                LDSM_X4(kb, uBf + off);
                uint32_t b0[2] = {kb[0], kb[2]};
                uint32_t b1[2] = {kb[1], kb[3]};
#pragma unroll
                for (int mt = 0; mt < 2; mt++) {
                    MMA_F16(C[mt][2 * p], a_hi[mt], b0);
                    MMA_F16(C[mt][2 * p + 1], a_hi[mt], b1);
                    MMA_F16(C[mt][2 * p], a_lo[mt], b0);
                    MMA_F16(C[mt][2 * p + 1], a_lo[mt], b1);
                }
            }
        }
        __syncthreads();
        if (s + 2 < NST) ISSUE(s + 2);
    }
#undef ISSUE

    // ---- epilogue ----
#pragma unroll
    for (int mt = 0; mt < 2; mt++) {
#pragma unroll
        for (int nt = 0; nt < 8; nt++) {
            int gm0 = m0 + warpM * 32 + mt * 16 + g;
            int gn = n0 + warpN * 64 + nt * 8 + qp * 2;
            float2 v0 = make_float2(C[mt][nt][0], C[mt][nt][1]);
            float2 v1 = make_float2(C[mt][nt][2], C[mt][nt][3]);
            if (MODE == 0) {
                int which = gn >> 11;
                int rem = gn & 2047;
                int h = rem >> 7;
                int d = rem & 127;
#pragma unroll
                for (int rr = 0; rr < 2; rr++) {
                    int gm = gm0 + rr * 8;
                    int b = gm >> 11;
                    int s = gm & 2047;
                    size_t off = (size_t)which * ((size_t)BNHS * HD_) +
                                 (((size_t)(b * NH_ + h)) * S_ + s) * HD_ + d;
                    *(float2*)&g_qkv[off] = rr ? v1 : v0;
                }
            } else {
                *(float2*)&Cout[(size_t)gm0 * HID_ + gn] = v0;
                *(float2*)&Cout[(size_t)(gm0 + 8) * HID_ + gn] = v1;
            }
        }
    }
}

// ---------------------------------------------------------------------------
// RoPE + convert: Q -> (qh, ql) fp16 split; K -> kf fp16; V -> vf fp16.
// ---------------------------------------------------------------------------
__global__ __launch_bounds__(256)
void rope_conv_kernel(const float* __restrict__ cosT, const float* __restrict__ sinT) {
    long long t = (long long)blockIdx.x * 256 + threadIdx.x;
    int d = (int)(t & 63);
    long long row = t >> 6;                 // 0 .. 3*BNHS-1
    int which = (int)(row / BNHS);
    long long lr = row % BNHS;
    int s = (int)(lr % S_);
    const float* p = g_qkv + row * HD_;
    float x1 = p[d];
    float x2 = p[d + 64];

    if (which < 2) {
        float c1 = cosT[s * HD_ + d];
        float s1 = sinT[s * HD_ + d];
        float c2 = cosT[s * HD_ + d + 64];
        float s2 = sinT[s * HD_ + d + 64];
        float r1 = x1 * c1 - x2 * s1;
        float r2 = x2 * c2 + x1 * s2;
        if (which == 0) {
            float h1 = __half2float(__float2half_rn(r1));
            float h2 = __half2float(__float2half_rn(r2));
            g_qh[lr * HD_ + d] = __float2half_rn(r1);
            g_ql[lr * HD_ + d] = __float2half_rn(r1 - h1);
            g_qh[lr * HD_ + d + 64] = __float2half_rn(r2);
            g_ql[lr * HD_ + d + 64] = __float2half_rn(r2 - h2);
        } else {
            g_kf[lr * HD_ + d] = __float2half_rn(r1);
            g_kf[lr * HD_ + d + 64] = __float2half_rn(r2);
        }
    } else {
        g_vf[lr * HD_ + d] = __float2half_rn(x1);
        g_vf[lr * HD_ + d + 64] = __float2half_rn(x2);
    }
}

// ---------------------------------------------------------------------------
// 2-pass fp16 causal flash attention, pre-converted inputs.
// BQ=128, BK=64, 256 threads. Writes pre-split ctx (fp16 hi/lo).
// ---------------------------------------------------------------------------
#define STQ 136
#define ATTN_SMEM ((2 * 128 + 2 * 64) * STQ * 2)   // 104448 bytes

__global__ __launch_bounds__(256, 1)
void attn_mma_kernel() {
    extern __shared__ char smraw[];
    h16* sQh = (h16*)smraw;
    h16* sQl = sQh + 128 * STQ;
    h16* sKf = sQl + 128 * STQ;
    h16* sVf = sKf + 64 * STQ;

    const int tid = threadIdx.x;
    const int lane = tid & 31;
    const int w = tid >> 5;
    const int qp = lane & 3;
    const int g = lane >> 2;
    const int frow = lane & 15;
    const int fcol = (lane >> 4) << 3;

    const int qt = blockIdx.x;
    const int bh = blockIdx.y;
    const int b = bh >> 4;
    const int h = bh & 15;
    const int q0 = qt * 128;

    const size_t hs = (size_t)S_ * HD_;
    const h16* Qh = g_qh + (size_t)bh * hs;
    const h16* Ql = g_ql + (size_t)bh * hs;
    const h16* Kf = g_kf + (size_t)bh * hs;
    const h16* Vf = g_vf + (size_t)bh * hs;

    // ---- load Q tile (128 x 128) hi/lo fp16 ----
#pragma unroll
    for (int i = 0; i < 8; i++) {
        int idx = tid + i * 256;
        int r = idx >> 4;
        int dd = (idx & 15) * 8;
        size_t ga = (size_t)(q0 + r) * HD_ + dd;
        *(uint4*)&sQh[r * STQ + dd] = *(const uint4*)&Qh[ga];
        *(uint4*)&sQl[r * STQ + dd] = *(const uint4*)&Ql[ga];
    }

    const uint32_t uQh = s2u(sQh), uQl = s2u(sQl);
    const uint32_t uKf = s2u(sKf), uVf = s2u(sVf);

    float O[16][4];
#pragma unroll
    for (int t = 0; t < 16; t++)
#pragma unroll
        for (int r = 0; r < 4; r++) O[t][r] = 0.f;
    float m0 = -1e30f, m1 = -1e30f, l0 = 0.f, l1 = 0.f;

    const float sc = 0.08838834764831845f;
    const int row0 = q0 + w * 16 + g;
    const int row1 = row0 + 8;

    __syncthreads();

    const int ktn = (q0 + 128) >> 6;
    for (int kt = 0; kt < ktn; kt++) {
        const int k0 = kt * 64;
#pragma unroll
        for (int i = 0; i < 4; i++) {
            int idx = tid + i * 256;
            int r = idx >> 4;
            int dd = (idx & 15) * 8;
            size_t ga = (size_t)(k0 + r) * HD_ + dd;
            *(uint4*)&sKf[r * STQ + dd] = *(const uint4*)&Kf[ga];
            *(uint4*)&sVf[r * STQ + dd] = *(const uint4*)&Vf[ga];
        }
        __syncthreads();

        const bool active = (k0 <= q0 + w * 16 + 15);
        if (active) {
            float S[8][4];
#pragma unroll
            for (int t = 0; t < 8; t++)
#pragma unroll
                for (int r = 0; r < 4; r++) S[t][r] = 0.f;

#pragma unroll
            for (int kc = 0; kc < 8; kc++) {
                const int col = kc * 16 + fcol;
                uint32_t qh[4], ql[4];
                uint32_t qoff = ((w * 16 + frow) * STQ + col) * 2;
                LDSM_X4(qh, uQh + qoff);
                LDSM_X4(ql, uQl + qoff);
#pragma unroll
                for (int p = 0; p < 4; p++) {
                    uint32_t koff = ((p * 16 + frow) * STQ + col) * 2;
                    uint32_t kf[4];
                    LDSM_X4(kf, uKf + koff);
                    uint32_t b0[2] = {kf[0], kf[2]};
                    uint32_t b1[2] = {kf[1], kf[3]};
                    MMA_F16(S[2 * p], qh, b0);
                    MMA_F16(S[2 * p + 1], qh, b1);
                    MMA_F16(S[2 * p], ql, b0);
                    MMA_F16(S[2 * p + 1], ql, b1);
                }
            }

            const bool maskneed = (k0 + 63 > row0);
#pragma unroll
            for (int t = 0; t < 8; t++) {
                int c0 = k0 + 8 * t + 2 * qp;
#pragma unroll
                for (int r = 0; r < 4; r++) {
                    S[t][r] *= sc;
                    if (maskneed) {
                        int colg = c0 + (r & 1);
                        int rowg = (r < 2) ? row0 : row1;
                        if (colg > rowg) S[t][r] = -1e9f;
                    }
                }
            }

            float rm0 = -1e30f, rm1 = -1e30f;
#pragma unroll
            for (int t = 0; t < 8; t++) {
                rm0 = fmaxf(rm0, fmaxf(S[t][0], S[t][1]));
                rm1 = fmaxf(rm1, fmaxf(S[t][2], S[t][3]));
            }
            rm0 = fmaxf(rm0, __shfl_xor_sync(0xffffffffu, rm0, 1));
            rm0 = fmaxf(rm0, __shfl_xor_sync(0xffffffffu, rm0, 2));
            rm1 = fmaxf(rm1, __shfl_xor_sync(0xffffffffu, rm1, 1));
            rm1 = fmaxf(rm1, __shfl_xor_sync(0xffffffffu, rm1, 2));
            float mn0 = fmaxf(m0, rm0), mn1 = fmaxf(m1, rm1);
            float a0 = __expf(m0 - mn0), a1 = __expf(m1 - mn1);
            float rs0 = 0.f, rs1 = 0.f;
#pragma unroll
            for (int t = 0; t < 8; t++) {
                S[t][0] = __expf(S[t][0] - mn0);
                S[t][1] = __expf(S[t][1] - mn0);
                S[t][2] = __expf(S[t][2] - mn1);
                S[t][3] = __expf(S[t][3] - mn1);
                rs0 += S[t][0] + S[t][1];
                rs1 += S[t][2] + S[t][3];
            }
            rs0 += __shfl_xor_sync(0xffffffffu, rs0, 1);
            rs0 += __shfl_xor_sync(0xffffffffu, rs0, 2);
            rs1 += __shfl_xor_sync(0xffffffffu, rs1, 1);
            rs1 += __shfl_xor_sync(0xffffffffu, rs1, 2);
            l0 = l0 * a0 + rs0;
            l1 = l1 * a1 + rs1;
            m0 = mn0;
            m1 = mn1;
#pragma unroll
            for (int t = 0; t < 16; t++) {
                O[t][0] *= a0; O[t][1] *= a0;
                O[t][2] *= a1; O[t][3] *= a1;
            }

            uint32_t ph[4][4], pl[4][4];
#pragma unroll
            for (int kc2 = 0; kc2 < 4; kc2++) {
                int t0 = 2 * kc2, t1 = 2 * kc2 + 1;
                float src[8] = {S[t0][0], S[t0][1], S[t0][2], S[t0][3],
                                S[t1][0], S[t1][1], S[t1][2], S[t1][3]};
                float hv[8], lv[8];
#pragma unroll
                for (int e = 0; e < 8; e++) {
                    hv[e] = __half2float(__float2half_rn(src[e]));
                    lv[e] = src[e] - hv[e];
                }
                ph[kc2][0] = packh(hv[0], hv[1]);
                ph[kc2][1] = packh(hv[2], hv[3]);
                ph[kc2][2] = packh(hv[4], hv[5]);
                ph[kc2][3] = packh(hv[6], hv[7]);
                pl[kc2][0] = packh(lv[0], lv[1]);
                pl[kc2][1] = packh(lv[2], lv[3]);
                pl[kc2][2] = packh(lv[4], lv[5]);
                pl[kc2][3] = packh(lv[6], lv[7]);
            }

#pragma unroll
            for (int kc2 = 0; kc2 < 4; kc2++) {
#pragma unroll
                for (int p = 0; p < 8; p++) {
                    uint32_t voff = ((kc2 * 16 + frow) * STQ + p * 16 + fcol) * 2;
                    uint32_t vf[4];
                    LDSM_X4T(vf, uVf + voff);
                    uint32_t b0[2] = {vf[0], vf[1]};
                    uint32_t b1[2] = {vf[2], vf[3]};
                    MMA_F16(O[2 * p], ph[kc2], b0);
                    MMA_F16(O[2 * p + 1], ph[kc2], b1);
                    MMA_F16(O[2 * p], pl[kc2], b0);
                    MMA_F16(O[2 * p + 1], pl[kc2], b1);
                }
            }
        }
        __syncthreads();
    }

    // ---- normalize + write pre-split ctx [b][s][h][d] ----
    float inv0 = 1.f / l0, inv1 = 1.f / l1;
    size_t base0 = (((size_t)b * S_ + row0) * NH_ + h) * HD_;
    size_t base1 = (((size_t)b * S_ + row1) * NH_ + h) * HD_;
#pragma unroll
    for (int t = 0; t < 16; t++) {
        int d = 8 * t + 2 * qp;
        float o0 = O[t][0] * inv0, o1 = O[t][1] * inv0;
        float o2 = O[t][2] * inv1, o3 = O[t][3] * inv1;
        float h0 = __half2float(__float2half_rn(o0));
        float h1 = __half2float(__float2half_rn(o1));
        float h2 = __half2float(__float2half_rn(o2));
        float h3 = __half2float(__float2half_rn(o3));
        *(uint32_t*)&g_ctxh[base0 + d] = packh(h0, h1);
        *(uint32_t*)&g_ctxl[base0 + d] = packh(o0 - h0, o1 - h1);
        *(uint32_t*)&g_ctxh[base1 + d] = packh(h2, h3);
        *(uint32_t*)&g_ctxl[base1 + d] = packh(o2 - h2, o3 - h3);
    }
}

// ---------------------------------------------------------------------------
extern "C" void kernel_launch(void* const* d_in, const int* in_sizes, int n_in,
                              void* d_out, int out_size) {
    (void)in_sizes; (void)n_in; (void)out_size;
    const float* x     = (const float*)d_in[0];
    const float* w_qkv = (const float*)d_in[1];
    const float* w_o   = (const float*)d_in[2];
    const float* cosT  = (const float*)d_in[3];
    const float* sinT  = (const float*)d_in[4];
    float* out = (float*)d_out;

    cudaFuncSetAttribute(attn_mma_kernel, cudaFuncAttributeMaxDynamicSharedMemorySize, ATTN_SMEM);
    cudaFuncSetAttribute(gemm_f16_kernel<0>, cudaFuncAttributeMaxDynamicSharedMemorySize, GSMEM);
    cudaFuncSetAttribute(gemm_f16_kernel<1>, cudaFuncAttributeMaxDynamicSharedMemorySize, GSMEM);

    h16 *xh, *xl, *wqf, *wof, *ctxh, *ctxl;
    cudaGetSymbolAddress((void**)&xh, g_xh);
    cudaGetSymbolAddress((void**)&xl, g_xl);
    cudaGetSymbolAddress((void**)&wqf, g_wqf);
    cudaGetSymbolAddress((void**)&wof, g_wof);
    cudaGetSymbolAddress((void**)&ctxh, g_ctxh);
    cudaGetSymbolAddress((void**)&ctxl, g_ctxl);

    int n4x = (B_ * S_ * HID_) / 4;
    int n4q = (3 * HID_ * HID_) / 4;
    int n4o = (HID_ * HID_) / 4;

    // 0) prep conversions
    split_kernel<<<(n4x + 255) / 256, 256>>>(x, xh, xl, n4x);
    conv_kernel<<<(n4q + 255) / 256, 256>>>(w_qkv, wqf, n4q);
    conv_kernel<<<(n4o + 255) / 256, 256>>>(w_o, wof, n4o);

    // 1) QKV projection
    gemm_f16_kernel<0><<<dim3(6144 / 128, 4096 / 128), 256, GSMEM>>>(xh, xl, wqf, nullptr);

    // 2) RoPE + convert q/k/v to fp16 (q split)
    rope_conv_kernel<<<(3 * BNHS * 64) / 256, 256>>>(cosT, sinT);

    // 3) Flash attention
    attn_mma_kernel<<<dim3(S_ / 128, B_ * NH_), 256, ATTN_SMEM>>>();

    // 4) Output projection
    gemm_f16_kernel<1><<<dim3(2048 / 128, 4096 / 128), 256, GSMEM>>>(ctxh, ctxl, wof, out);
}

// round 13
// speedup vs baseline: 1.5647x; 1.0185x over previous
#include <cuda_runtime.h>
#include <cuda_fp16.h>
#include <cstdint>
#include <math.h>

#define B_   2
#define S_   2048
#define HID_ 2048
#define NH_  16
#define HD_  128
#define KDIM 2048
#define BNHS (B_ * NH_ * S_)

typedef __half h16;

// ---- persistent buffers ----
__device__ float g_qkv[(size_t)3 * BNHS * HD_];   // [which][b][h][s][d] fp32
__device__ h16 g_xh[(size_t)B_ * S_ * HID_];
__device__ h16 g_xl[(size_t)B_ * S_ * HID_];
__device__ h16 g_wqf[(size_t)3 * HID_ * HID_];
__device__ h16 g_wof[(size_t)HID_ * HID_];
__device__ h16 g_qh[(size_t)BNHS * HD_];
__device__ h16 g_ql[(size_t)BNHS * HD_];
__device__ h16 g_kf[(size_t)BNHS * HD_];
__device__ h16 g_vf[(size_t)BNHS * HD_];
__device__ h16 g_ctxh[(size_t)B_ * S_ * HID_];    // [b][s][h][d]
__device__ h16 g_ctxl[(size_t)B_ * S_ * HID_];

// ---------------- helpers ----------------
__device__ __forceinline__ uint32_t s2u(const void* p) {
    return (uint32_t)__cvta_generic_to_shared(p);
}
__device__ __forceinline__ uint32_t packh(float lo, float hi) {
    uint32_t r;
    asm("cvt.rn.f16x2.f32 %0, %1, %2;" : "=r"(r) : "f"(hi), "f"(lo));
    return r;
}

#define MMA_F16(d, a, b)                                                      \
    asm volatile(                                                             \
        "mma.sync.aligned.m16n8k16.row.col.f32.f16.f16.f32 "                  \
        "{%0,%1,%2,%3}, {%4,%5,%6,%7}, {%8,%9}, {%0,%1,%2,%3};\n"             \
        : "+f"((d)[0]), "+f"((d)[1]), "+f"((d)[2]), "+f"((d)[3])              \
        : "r"((a)[0]), "r"((a)[1]), "r"((a)[2]), "r"((a)[3]),                 \
          "r"((b)[0]), "r"((b)[1]))

#define LDSM_X4(r, addr)                                                      \
    asm volatile("ldmatrix.sync.aligned.m8n8.x4.shared.b16 {%0,%1,%2,%3}, [%4];" \
                 : "=r"((r)[0]), "=r"((r)[1]), "=r"((r)[2]), "=r"((r)[3])     \
                 : "r"(addr))

#define LDSM_X4T(r, addr)                                                     \
    asm volatile("ldmatrix.sync.aligned.m8n8.x4.trans.shared.b16 {%0,%1,%2,%3}, [%4];" \
                 : "=r"((r)[0]), "=r"((r)[1]), "=r"((r)[2]), "=r"((r)[3])     \
                 : "r"(addr))

#define CP_ASYNC16(dst, src)                                                  \
    asm volatile("cp.async.cg.shared.global [%0], [%1], 16;" ::               \
                 "r"(dst), "l"(src))
#define CP_COMMIT() asm volatile("cp.async.commit_group;" ::: "memory")
#define CP_WAIT1()  asm volatile("cp.async.wait_group 1;" ::: "memory")
#define CP_WAIT0()  asm volatile("cp.async.wait_group 0;" ::: "memory")

// ---------------------------------------------------------------------------
// Prep: split fp32 -> fp16 hi/lo, and plain fp32 -> fp16 convert.
// ---------------------------------------------------------------------------
__global__ __launch_bounds__(256)
void split_kernel(const float* __restrict__ src, h16* __restrict__ h,
                  h16* __restrict__ l, int n4) {
    int i = blockIdx.x * 256 + threadIdx.x;
    if (i >= n4) return;
    float4 v = *(const float4*)&src[(size_t)i * 4];
    float f[4] = {v.x, v.y, v.z, v.w};
    float hf[4], lf[4];
#pragma unroll
    for (int e = 0; e < 4; e++) {
        hf[e] = __half2float(__float2half_rn(f[e]));
        lf[e] = f[e] - hf[e];
    }
    *(uint2*)&h[(size_t)i * 4] = make_uint2(packh(hf[0], hf[1]), packh(hf[2], hf[3]));
    *(uint2*)&l[(size_t)i * 4] = make_uint2(packh(lf[0], lf[1]), packh(lf[2], lf[3]));
}

__global__ __launch_bounds__(256)
void conv_kernel(const float* __restrict__ src, h16* __restrict__ dst, int n4) {
    int i = blockIdx.x * 256 + threadIdx.x;
    if (i >= n4) return;
    float4 v = *(const float4*)&src[(size_t)i * 4];
    *(uint2*)&dst[(size_t)i * 4] = make_uint2(packh(v.x, v.y), packh(v.z, v.w));
}

// ---------------------------------------------------------------------------
// Pre-split 2-pass fp16 GEMM, 3-stage cp.async pipeline, 1 barrier/stage.
// C[m][n] = sum_k A[m][k]*W[n][k]; A = Ah+Al fp16, W fp16.
// BM=BN=128, BK=32/stage, 256 thr, 8 warps (4Mx2N), warp tile 32x64.
// ---------------------------------------------------------------------------
#define GST 40                        // halfs per row (32 + 8 pad)
#define ARRB (128 * GST * 2)          // bytes per array = 10240
#define STGB (3 * ARRB)               // bytes per stage = 30720
#define GSMEM (3 * STGB)              // 92160 (3 stages)

template <int MODE>
__global__ __launch_bounds__(256, 2)
void gemm_f16_kernel(const h16* __restrict__ Agh, const h16* __restrict__ Agl,
                     const h16* __restrict__ Bgf, float* __restrict__ Cout) {
    extern __shared__ char smem[];
    const uint32_t sbase = s2u(smem);
    const int m0 = blockIdx.y * 128;
    const int n0 = blockIdx.x * 128;
    const int tid = threadIdx.x;
    const int lane = tid & 31;
    const int warp = tid >> 5;
    const int warpM = warp & 3;
    const int warpN = warp >> 2;

    const int g = lane >> 2;
    const int qp = lane & 3;
    const int frow = lane & 15;
    const int fcol = (lane >> 4) << 3;

    float C[2][8][4];
#pragma unroll
    for (int mt = 0; mt < 2; mt++)
#pragma unroll
        for (int nt = 0; nt < 8; nt++)
#pragma unroll
            for (int r = 0; r < 4; r++) C[mt][nt][r] = 0.f;

#define ISSUE(s)                                                              \
    do {                                                                      \
        const int k0_ = (s) * 32;                                             \
        const uint32_t sb_ = sbase + ((s) % 3) * STGB;                        \
        _Pragma("unroll")                                                     \
        for (int t = 0; t < 2; t++) {                                         \
            int idx = tid + t * 256;                                          \
            int row = idx >> 2;                                               \
            int qtr = (idx & 3) * 8;                                          \
            uint32_t soff = (row * GST + qtr) * 2;                            \
            size_t ga = (size_t)(m0 + row) * KDIM + k0_ + qtr;                \
            size_t gb = (size_t)(n0 + row) * KDIM + k0_ + qtr;                \
            CP_ASYNC16(sb_ + soff,            Agh + ga);                      \
            CP_ASYNC16(sb_ + ARRB + soff,     Agl + ga);                      \
            CP_ASYNC16(sb_ + 2 * ARRB + soff, Bgf + gb);                      \
        }                                                                     \
        CP_COMMIT();                                                          \
    } while (0)

    ISSUE(0);
    ISSUE(1);

    const int NST = KDIM / 32;   // 64
#pragma unroll 1
    for (int s = 0; s < NST; s++) {
        if (s == NST - 1) CP_WAIT0(); else CP_WAIT1();
        __syncthreads();
        // Buffer (s+2)%3 was consumed at stage s-1; the barrier above proves
        // every warp finished stage s-1, so refilling it now is safe.
        if (s + 2 < NST) ISSUE(s + 2);

        const uint32_t uAh = sbase + (s % 3) * STGB;
        const uint32_t uAl = uAh + ARRB;
        const uint32_t uBf = uAh + 2 * ARRB;

#pragma unroll
        for (int kc = 0; kc < 2; kc++) {
            const int col = kc * 16 + fcol;
            uint32_t a_hi[2][4], a_lo[2][4];
#pragma unroll
            for (int mt = 0; mt < 2; mt++) {
                uint32_t off = ((warpM * 32 + mt * 16 + frow) * GST + col) * 2;
                LDSM_X4(a_hi[mt], uAh + off);
                LDSM_X4(a_lo[mt], uAl + off);
            }
#pragma unroll
            for (int p = 0; p < 4; p++) {
                uint32_t off = ((warpN * 64 + p * 16 + frow) * GST + col) * 2;
                uint32_t kb[4];
                LDSM_X4(kb, uBf + off);
                uint32_t b0[2] = {kb[0], kb[2]};
                uint32_t b1[2] = {kb[1], kb[3]};
#pragma unroll
                for (int mt = 0; mt < 2; mt++) {
                    MMA_F16(C[mt][2 * p], a_hi[mt], b0);
                    MMA_F16(C[mt][2 * p + 1], a_hi[mt], b1);
                    MMA_F16(C[mt][2 * p], a_lo[mt], b0);
                    MMA_F16(C[mt][2 * p + 1], a_lo[mt], b1);
                }
            }
        }
    }
#undef ISSUE

    // ---- epilogue ----
#pragma unroll
    for (int mt = 0; mt < 2; mt++) {
#pragma unroll
        for (int nt = 0; nt < 8; nt++) {
            int gm0 = m0 + warpM * 32 + mt * 16 + g;
            int gn = n0 + warpN * 64 + nt * 8 + qp * 2;
            float2 v0 = make_float2(C[mt][nt][0], C[mt][nt][1]);
            float2 v1 = make_float2(C[mt][nt][2], C[mt][nt][3]);
            if (MODE == 0) {
                int which = gn >> 11;
                int rem = gn & 2047;
                int h = rem >> 7;
                int d = rem & 127;
#pragma unroll
                for (int rr = 0; rr < 2; rr++) {
                    int gm = gm0 + rr * 8;
                    int b = gm >> 11;
                    int s = gm & 2047;
                    size_t off = (size_t)which * ((size_t)BNHS * HD_) +
                                 (((size_t)(b * NH_ + h)) * S_ + s) * HD_ + d;
                    *(float2*)&g_qkv[off] = rr ? v1 : v0;
                }
            } else {
                *(float2*)&Cout[(size_t)gm0 * HID_ + gn] = v0;
                *(float2*)&Cout[(size_t)(gm0 + 8) * HID_ + gn] = v1;
            }
        }
    }
}

// ---------------------------------------------------------------------------
// RoPE + convert: Q -> (qh, ql) fp16 split; K -> kf fp16; V -> vf fp16.
// ---------------------------------------------------------------------------
__global__ __launch_bounds__(256)
void rope_conv_kernel(const float* __restrict__ cosT, const float* __restrict__ sinT) {
    long long t = (long long)blockIdx.x * 256 + threadIdx.x;
    int d = (int)(t & 63);
    long long row = t >> 6;                 // 0 .. 3*BNHS-1
    int which = (int)(row / BNHS);
    long long lr = row % BNHS;
    int s = (int)(lr % S_);
    const float* p = g_qkv + row * HD_;
    float x1 = p[d];
    float x2 = p[d + 64];

    if (which < 2) {
        float c1 = cosT[s * HD_ + d];
        float s1 = sinT[s * HD_ + d];
        float c2 = cosT[s * HD_ + d + 64];
        float s2 = sinT[s * HD_ + d + 64];
        float r1 = x1 * c1 - x2 * s1;
        float r2 = x2 * c2 + x1 * s2;
        if (which == 0) {
            float h1 = __half2float(__float2half_rn(r1));
            float h2 = __half2float(__float2half_rn(r2));
            g_qh[lr * HD_ + d] = __float2half_rn(r1);
            g_ql[lr * HD_ + d] = __float2half_rn(r1 - h1);
            g_qh[lr * HD_ + d + 64] = __float2half_rn(r2);
            g_ql[lr * HD_ + d + 64] = __float2half_rn(r2 - h2);
        } else {
            g_kf[lr * HD_ + d] = __float2half_rn(r1);
            g_kf[lr * HD_ + d + 64] = __float2half_rn(r2);
        }
    } else {
        g_vf[lr * HD_ + d] = __float2half_rn(x1);
        g_vf[lr * HD_ + d + 64] = __float2half_rn(x2);
    }
}

// ---------------------------------------------------------------------------
// 2-pass fp16 causal flash attention, cp.async K/V double buffer,
// ONE barrier per kt. BQ=128, BK=64, 256 threads.
// ---------------------------------------------------------------------------
#define STQ 136
#define KVB (64 * STQ * 2)                         // bytes per K or V tile
#define ATTN_SMEM ((2 * 128) * STQ * 2 + 4 * KVB)  // Q hi/lo + 2x(K,V)

__global__ __launch_bounds__(256, 1)
void attn_mma_kernel() {
    extern __shared__ char smraw[];
    h16* sQh = (h16*)smraw;
    h16* sQl = sQh + 128 * STQ;
    char* kvbase = (char*)(sQl + 128 * STQ);
    // layout: [buf0: K,V][buf1: K,V]
    const uint32_t ukv = s2u(kvbase);

    const int tid = threadIdx.x;
    const int lane = tid & 31;
    const int w = tid >> 5;
    const int qp = lane & 3;
    const int g = lane >> 2;
    const int frow = lane & 15;
    const int fcol = (lane >> 4) << 3;

    const int qt = blockIdx.x;
    const int bh = blockIdx.y;
    const int b = bh >> 4;
    const int h = bh & 15;
    const int q0 = qt * 128;

    const size_t hs = (size_t)S_ * HD_;
    const h16* Qh = g_qh + (size_t)bh * hs;
    const h16* Ql = g_ql + (size_t)bh * hs;
    const h16* Kf = g_kf + (size_t)bh * hs;
    const h16* Vf = g_vf + (size_t)bh * hs;

    // ---- load Q tile (128 x 128) hi/lo fp16 ----
#pragma unroll
    for (int i = 0; i < 8; i++) {
        int idx = tid + i * 256;
        int r = idx >> 4;
        int dd = (idx & 15) * 8;
        size_t ga = (size_t)(q0 + r) * HD_ + dd;
        *(uint4*)&sQh[r * STQ + dd] = *(const uint4*)&Qh[ga];
        *(uint4*)&sQl[r * STQ + dd] = *(const uint4*)&Ql[ga];
    }

    const uint32_t uQh = s2u(sQh), uQl = s2u(sQl);

    float O[16][4];
#pragma unroll
    for (int t = 0; t < 16; t++)
#pragma unroll
        for (int r = 0; r < 4; r++) O[t][r] = 0.f;
    float m0 = -1e30f, m1 = -1e30f, l0 = 0.f, l1 = 0.f;

    const float sc = 0.08838834764831845f;
    const int row0 = q0 + w * 16 + g;
    const int row1 = row0 + 8;

    // cp.async K/V tile loader: 64 rows x 128 halfs; 1024 x 16B chunks / 2 arrays
    // per thread: 4 chunks (2 per array). idx = tid + t*256: row=idx>>4, dd=(idx&15)*8
#define KV_ISSUE(kt_)                                                         \
    do {                                                                      \
        const int kk0 = (kt_) * 64;                                           \
        const uint32_t kb_ = ukv + ((kt_) & 1) * (2 * KVB);                   \
        _Pragma("unroll")                                                     \
        for (int t = 0; t < 4; t++) {                                         \
            int idx = tid + t * 256;                                          \
            int r = idx >> 4;                                                 \
            int dd = (idx & 15) * 8;                                          \
            uint32_t soff = (r * STQ + dd) * 2;                               \
            size_t ga = (size_t)(kk0 + r) * HD_ + dd;                         \
            CP_ASYNC16(kb_ + soff,       Kf + ga);                            \
            CP_ASYNC16(kb_ + KVB + soff, Vf + ga);                            \
        }                                                                     \
        CP_COMMIT();                                                          \
    } while (0)

    KV_ISSUE(0);

    const int ktn = (q0 + 128) >> 6;
#pragma unroll 1
    for (int kt = 0; kt < ktn; kt++) {
        const int k0 = kt * 64;
        CP_WAIT0();
        __syncthreads();
        if (kt + 1 < ktn) KV_ISSUE(kt + 1);

        const uint32_t uKf = ukv + (kt & 1) * (2 * KVB);
        const uint32_t uVf = uKf + KVB;

        const bool active = (k0 <= q0 + w * 16 + 15);
        if (active) {
            float S[8][4];
#pragma unroll
            for (int t = 0; t < 8; t++)
#pragma unroll
                for (int r = 0; r < 4; r++) S[t][r] = 0.f;

#pragma unroll
            for (int kc = 0; kc < 8; kc++) {
                const int col = kc * 16 + fcol;
                uint32_t qh[4], ql[4];
                uint32_t qoff = ((w * 16 + frow) * STQ + col) * 2;
                LDSM_X4(qh, uQh + qoff);
                LDSM_X4(ql, uQl + qoff);
#pragma unroll
                for (int p = 0; p < 4; p++) {
                    uint32_t koff = ((p * 16 + frow) * STQ + col) * 2;
                    uint32_t kf[4];
                    LDSM_X4(kf, uKf + koff);
                    uint32_t b0[2] = {kf[0], kf[2]};
                    uint32_t b1[2] = {kf[1], kf[3]};
                    MMA_F16(S[2 * p], qh, b0);
                    MMA_F16(S[2 * p + 1], qh, b1);
                    MMA_F16(S[2 * p], ql, b0);
                    MMA_F16(S[2 * p + 1], ql, b1);
                }
            }

            const bool maskneed = (k0 + 63 > row0);
#pragma unroll
            for (int t = 0; t < 8; t++) {
                int c0 = k0 + 8 * t + 2 * qp;
#pragma unroll
                for (int r = 0; r < 4; r++) {
                    S[t][r] *= sc;
                    if (maskneed) {
                        int colg = c0 + (r & 1);
                        int rowg = (r < 2) ? row0 : row1;
                        if (colg > rowg) S[t][r] = -1e9f;
                    }
                }
            }

            float rm0 = -1e30f, rm1 = -1e30f;
#pragma unroll
            for (int t = 0; t < 8; t++) {
                rm0 = fmaxf(rm0, fmaxf(S[t][0], S[t][1]));
                rm1 = fmaxf(rm1, fmaxf(S[t][2], S[t][3]));
            }
            rm0 = fmaxf(rm0, __shfl_xor_sync(0xffffffffu, rm0, 1));
            rm0 = fmaxf(rm0, __shfl_xor_sync(0xffffffffu, rm0, 2));
            rm1 = fmaxf(rm1, __shfl_xor_sync(0xffffffffu, rm1, 1));
            rm1 = fmaxf(rm1, __shfl_xor_sync(0xffffffffu, rm1, 2));
            float mn0 = fmaxf(m0, rm0), mn1 = fmaxf(m1, rm1);
            float a0 = __expf(m0 - mn0), a1 = __expf(m1 - mn1);
            float rs0 = 0.f, rs1 = 0.f;
#pragma unroll
            for (int t = 0; t < 8; t++) {
                S[t][0] = __expf(S[t][0] - mn0);
                S[t][1] = __expf(S[t][1] - mn0);
                S[t][2] = __expf(S[t][2] - mn1);
                S[t][3] = __expf(S[t][3] - mn1);
                rs0 += S[t][0] + S[t][1];
                rs1 += S[t][2] + S[t][3];
            }
            rs0 += __shfl_xor_sync(0xffffffffu, rs0, 1);
            rs0 += __shfl_xor_sync(0xffffffffu, rs0, 2);
            rs1 += __shfl_xor_sync(0xffffffffu, rs1, 1);
            rs1 += __shfl_xor_sync(0xffffffffu, rs1, 2);
            l0 = l0 * a0 + rs0;
            l1 = l1 * a1 + rs1;
            m0 = mn0;
            m1 = mn1;
#pragma unroll
            for (int t = 0; t < 16; t++) {
                O[t][0] *= a0; O[t][1] *= a0;
                O[t][2] *= a1; O[t][3] *= a1;
            }

            uint32_t ph[4][4], pl[4][4];
#pragma unroll
            for (int kc2 = 0; kc2 < 4; kc2++) {
                int t0 = 2 * kc2, t1 = 2 * kc2 + 1;
                float src[8] = {S[t0][0], S[t0][1], S[t0][2], S[t0][3],
                                S[t1][0], S[t1][1], S[t1][2], S[t1][3]};
                float hv[8], lv[8];
#pragma unroll
                for (int e = 0; e < 8; e++) {
                    hv[e] = __half2float(__float2half_rn(src[e]));
                    lv[e] = src[e] - hv[e];
                }
                ph[kc2][0] = packh(hv[0], hv[1]);
                ph[kc2][1] = packh(hv[2], hv[3]);
                ph[kc2][2] = packh(hv[4], hv[5]);
                ph[kc2][3] = packh(hv[6], hv[7]);
                pl[kc2][0] = packh(lv[0], lv[1]);
                pl[kc2][1] = packh(lv[2], lv[3]);
                pl[kc2][2] = packh(lv[4], lv[5]);
                pl[kc2][3] = packh(lv[6], lv[7]);
            }

#pragma unroll
            for (int kc2 = 0; kc2 < 4; kc2++) {
#pragma unroll
                for (int p = 0; p < 8; p++) {
                    uint32_t voff = ((kc2 * 16 + frow) * STQ + p * 16 + fcol) * 2;
                    uint32_t vf[4];
                    LDSM_X4T(vf, uVf + voff);
                    uint32_t b0[2] = {vf[0], vf[1]};
                    uint32_t b1[2] = {vf[2], vf[3]};
                    MMA_F16(O[2 * p], ph[kc2], b0);
                    MMA_F16(O[2 * p + 1], ph[kc2], b1);
                    MMA_F16(O[2 * p], pl[kc2], b0);
                    MMA_F16(O[2 * p + 1], pl[kc2], b1);
                }
            }
        }
    }
#undef KV_ISSUE

    // ---- normalize + write pre-split ctx [b][s][h][d] ----
    float inv0 = 1.f / l0, inv1 = 1.f / l1;
    size_t base0 = (((size_t)b * S_ + row0) * NH_ + h) * HD_;
    size_t base1 = (((size_t)b * S_ + row1) * NH_ + h) * HD_;
#pragma unroll
    for (int t = 0; t < 16; t++) {
        int d = 8 * t + 2 * qp;
        float o0 = O[t][0] * inv0, o1 = O[t][1] * inv0;
        float o2 = O[t][2] * inv1, o3 = O[t][3] * inv1;
        float h0 = __half2float(__float2half_rn(o0));
        float h1 = __half2float(__float2half_rn(o1));
        float h2 = __half2float(__float2half_rn(o2));
        float h3 = __half2float(__float2half_rn(o3));
        *(uint32_t*)&g_ctxh[base0 + d] = packh(h0, h1);
        *(uint32_t*)&g_ctxl[base0 + d] = packh(o0 - h0, o1 - h1);
        *(uint32_t*)&g_ctxh[base1 + d] = packh(h2, h3);
        *(uint32_t*)&g_ctxl[base1 + d] = packh(o2 - h2, o3 - h3);
    }
}

// ---------------------------------------------------------------------------
extern "C" void kernel_launch(void* const* d_in, const int* in_sizes, int n_in,
                              void* d_out, int out_size) {
    (void)in_sizes; (void)n_in; (void)out_size;
    const float* x     = (const float*)d_in[0];
    const float* w_qkv = (const float*)d_in[1];
    const float* w_o   = (const float*)d_in[2];
    const float* cosT  = (const float*)d_in[3];
    const float* sinT  = (const float*)d_in[4];
    float* out = (float*)d_out;

    cudaFuncSetAttribute(attn_mma_kernel, cudaFuncAttributeMaxDynamicSharedMemorySize, ATTN_SMEM);
    cudaFuncSetAttribute(gemm_f16_kernel<0>, cudaFuncAttributeMaxDynamicSharedMemorySize, GSMEM);
    cudaFuncSetAttribute(gemm_f16_kernel<1>, cudaFuncAttributeMaxDynamicSharedMemorySize, GSMEM);

    h16 *xh, *xl, *wqf, *wof, *ctxh, *ctxl;
    cudaGetSymbolAddress((void**)&xh, g_xh);
    cudaGetSymbolAddress((void**)&xl, g_xl);
    cudaGetSymbolAddress((void**)&wqf, g_wqf);
    cudaGetSymbolAddress((void**)&wof, g_wof);
    cudaGetSymbolAddress((void**)&ctxh, g_ctxh);
    cudaGetSymbolAddress((void**)&ctxl, g_ctxl);

    int n4x = (B_ * S_ * HID_) / 4;
    int n4q = (3 * HID_ * HID_) / 4;
    int n4o = (HID_ * HID_) / 4;

    split_kernel<<<(n4x + 255) / 256, 256>>>(x, xh, xl, n4x);
    conv_kernel<<<(n4q + 255) / 256, 256>>>(w_qkv, wqf, n4q);
    conv_kernel<<<(n4o + 255) / 256, 256>>>(w_o, wof, n4o);

    gemm_f16_kernel<0><<<dim3(6144 / 128, 4096 / 128), 256, GSMEM>>>(xh, xl, wqf, nullptr);
    rope_conv_kernel<<<(3 * BNHS * 64) / 256, 256>>>(cosT, sinT);
    attn_mma_kernel<<<dim3(S_ / 128, B_ * NH_), 256, ATTN_SMEM>>>();
    gemm_f16_kernel<1><<<dim3(2048 / 128, 4096 / 128), 256, GSMEM>>>(ctxh, ctxl, wof, out);
}